// round 13
// baseline (speedup 1.0000x reference)
#include <cuda_runtime.h>
#include <cuda_bf16.h>
#include <cstdint>
#include <cstddef>

#define NF   16000
#define KNBR 64
#define RADIUS_F ((float)(0.5*6.0*1.5*0.025))

// ---------------- scratch (device globals; no allocation APIs) ----------------
__device__ float  g_A[(size_t)NF * 64 * 96];   // bf16 A for layers 2/3; fp32 P for layer 4
__device__ float4 g_gF_ff[NF * KNBR];
__device__ int    g_gI_ff[NF * KNBR];
__device__ float4 g_gF_wf[NF * KNBR];
__device__ int    g_gI_wf[NF * KNBR];
__device__ float  g_out1[NF * 96];
__device__ __nv_bfloat16 g_out1b[NF * 96];     // bf16 mirror of out1 (cellgemm gather)
__device__ float  g_out2[NF * 64];
__device__ __nv_bfloat16 g_out2b[NF * 64];     // bf16 mirror of out2
__device__ float  g_out3[NF * 64];
__device__ float  g_dense[NF * 64];
__device__ uint32_t g_Wb2[3072 * 64];          // W_c2 packed bf16x2, [kp][n]
__device__ uint32_t g_Wb3[2048 * 64];          // W_c3 packed bf16x2
__device__ float  g_Wp4[64 * 256];             // W_c4 re-laid [c][cell*4+o], pad o=3 -> 0
__device__ int    g_mask_u8;

// ---------------- helpers ----------------
__device__ __forceinline__ uint32_t smem_u32(const void* p) {
    uint32_t a;
    asm("{ .reg .u64 t; cvta.to.shared.u64 t, %1; cvt.u32.u64 %0, t; }" : "=r"(a) : "l"(p));
    return a;
}
__device__ __forceinline__ void cp16(uint32_t dst, const void* src) {
    asm volatile("cp.async.cg.shared.global [%0], [%1], 16;" :: "r"(dst), "l"(src));
}
#define CP_COMMIT() asm volatile("cp.async.commit_group;" ::: "memory")
__device__ __forceinline__ uint32_t bf16x2(float hi, float lo) {
    uint32_t r;
    asm("cvt.rn.bf16x2.f32 %0, %1, %2;" : "=r"(r) : "f"(hi), "f"(lo));
    return r;
}
__device__ __forceinline__ float fast_sqrt_pos(float m) {   // m > 0
    return m * rsqrtf(m);
}

// ---------------- mask dtype detector ----------------
__global__ void detect_mask_kernel(const unsigned int* __restrict__ m)
{
    __shared__ int s;
    if (threadIdx.x == 0) s = 0;
    __syncthreads();
    int bad = 0;
    for (int i = threadIdx.x; i < 16384; i += blockDim.x)
        if (m[i] > 1u) { bad = 1; break; }
    if (bad) atomicOr(&s, 1);
    __syncthreads();
    if (threadIdx.x == 0) g_mask_u8 = s;
}

// ---------------- geometry (both neighbor sets, fast math) ----------------
static __device__ __forceinline__ float sgnf(float v) {
    return (v > 0.f) ? 1.f : ((v < 0.f) ? -1.f : 0.f);
}
__device__ __forceinline__ void gridmap(float u, int& i0, float& f) {
    float cc = (u * 0.5f + 0.5f) * 3.f;
    cc = fminf(fmaxf(cc, 0.f), 3.f);
    float fi = floorf(cc);
    fi = fminf(fi, 2.f);
    f = cc - fi;
    i0 = (int)fi;
}

__global__ void geom2_kernel(
    const float* __restrict__ fluid_pos, const float* __restrict__ wall_pos,
    const int* __restrict__ nbr_ff, const void* __restrict__ mask_ff,
    float4* __restrict__ gFff, int* __restrict__ gIff,
    const int* __restrict__ nbr_wf, const void* __restrict__ mask_wf,
    float4* __restrict__ gFwf, int* __restrict__ gIwf)
{
    int gidx = blockIdx.x * blockDim.x + threadIdx.x;
    if (gidx >= 2 * NF * KNBR) return;
    int which = gidx >= NF * KNBR;                 // uniform per block
    int idx = which ? gidx - NF * KNBR : gidx;
    const float* pin = which ? wall_pos : fluid_pos;
    const int*   nbr = which ? nbr_wf   : nbr_ff;
    const void*  mask = which ? mask_wf : mask_ff;
    float4* gF = which ? gFwf : gFff;
    int*    gI = which ? gIwf : gIff;

    int mv = g_mask_u8 ? (int)((const unsigned char*)mask)[idx]
                       : ((const int*)mask)[idx];
    if (mv == 0) { gF[idx] = make_float4(0.f, 0.f, 0.f, 0.f); gI[idx] = 0; return; }
    int n = idx >> 6;
    int j = nbr[idx];
    float x = (pin[j*3+0] - fluid_pos[n*3+0]) * (1.f / RADIUS_F);
    float y = (pin[j*3+1] - fluid_pos[n*3+1]) * (1.f / RADIUS_F);
    float z = (pin[j*3+2] - fluid_pos[n*3+2]) * (1.f / RADIUS_F);
    float sq = x*x + y*y + z*z;
    float t1 = 1.f - sq;
    float win = fminf(fmaxf(t1*t1*t1, 0.f), 1.f);

    const float eps = 1e-12f;
    float norm = fast_sqrt_pos(fmaxf(sq, eps));
    float rho  = fast_sqrt_pos(fmaxf(x*x + y*y, eps));
    bool  top  = (1.25f*z*z > x*x + y*y);
    float st_arg = __fdividef(3.f*norm, norm + fabsf(z));
    float s_top = fast_sqrt_pos(st_arg);
    float inv_rho_n = __fdividef(norm, rho);
    float xs = top ? x*s_top : x*inv_rho_n;
    float ys = top ? y*s_top : y*inv_rho_n;
    float zs = top ? sgnf(z)*norm : 1.5f*z;
    if (sq < eps) { xs = 0.f; ys = 0.f; zs = 0.f; }
    float rxy = fast_sqrt_pos(fmaxf(xs*xs + ys*ys, eps));
    bool use_x = fabsf(ys) <= fabsf(xs);
    float ddx = (use_x  && fabsf(xs) > eps) ? xs : 1.f;
    float ddy = (!use_x && fabsf(ys) > eps) ? ys : 1.f;
    const float c4 = 1.27323954473516276487f;  // 4/pi
    float xc = use_x ? sgnf(xs)*rxy : sgnf(ys)*rxy*c4*atanf(__fdividef(xs, ddy));
    float yc = use_x ? sgnf(xs)*rxy*c4*atanf(__fdividef(ys, ddx)) : sgnf(ys)*rxy;
    if (xs*xs + ys*ys < eps) { xc = 0.f; yc = 0.f; }

    int ix, iy, iz; float fx, fy, fz;
    gridmap(xc, ix, fx); gridmap(yc, iy, fy); gridmap(zs, iz, fz);
    gF[idx] = make_float4(fx, fy, fz, win);
    gI[idx] = (ix*4 + iy)*4 + iz;
}

// ---------------- layer-1 cconv (cin=3, cout=32), W staged in smem (split, proven) --------
__global__ __launch_bounds__(256) void conv1_kernel(
    const float* __restrict__ feat, const int* __restrict__ nbr,
    const float4* __restrict__ gF, const int* __restrict__ gI,
    const float* __restrict__ W, const float* __restrict__ b,
    float* __restrict__ out1, __nv_bfloat16* __restrict__ out1b, int col0)
{
    __shared__ float A[4][192];
    __shared__ float sW[192 * 32];
    __shared__ float red[256];
    int t = threadIdx.x;
    int p = t >> 6, tl = t & 63;
    int n = blockIdx.x * 4 + p;
    float* Ap = A[p];
    Ap[tl] = 0.f; Ap[tl + 64] = 0.f; Ap[tl + 128] = 0.f;
    #pragma unroll
    for (int i = 0; i < 24; i++) sW[i * 256 + t] = W[i * 256 + t];
    __syncthreads();

    int idx = n * KNBR + tl;
    float4 g = gF[idx];
    if (g.w != 0.f) {
        int j = nbr[idx];
        float f0 = feat[j*3+0]*g.w, f1 = feat[j*3+1]*g.w, f2 = feat[j*3+2]*g.w;
        int base = gI[idx];
        float wx[2] = {1.f - g.x, g.x};
        float wy[2] = {1.f - g.y, g.y};
        float wz[2] = {1.f - g.z, g.z};
        #pragma unroll
        for (int cx = 0; cx < 2; cx++)
        #pragma unroll
        for (int cy = 0; cy < 2; cy++)
        #pragma unroll
        for (int cz = 0; cz < 2; cz++) {
            float wc = wx[cx]*wy[cy]*wz[cz];
            int cell = base + cx*16 + cy*4 + cz;
            atomicAdd(&Ap[cell*3+0], wc*f0);
            atomicAdd(&Ap[cell*3+1], wc*f1);
            atomicAdd(&Ap[cell*3+2], wc*f2);
        }
    }
    __syncthreads();

    int o = tl & 31, h = tl >> 5;
    float acc = 0.f;
    #pragma unroll 8
    for (int i = h*96; i < h*96 + 96; i++)
        acc += Ap[i] * sW[i*32 + o];
    red[t] = acc;
    __syncthreads();
    if (tl < 32) {
        float v = red[p*64 + tl] + red[p*64 + tl + 32] + b[o];
        v = fmaxf(v, 0.f);
        out1 [n*96 + col0 + tl] = v;
        out1b[n*96 + col0 + tl] = __float2bfloat16(v);
    }
}

// ---------------- cellgemm: A[n] = S[n] @ F[n] on tensor cores (layers 2/3) ----------------
#define S_WLDS 36
template<int CIN>
__global__ __launch_bounds__(128) void cellgemm_kernel(
    const __nv_bfloat16* __restrict__ featb, const int* __restrict__ nbr,
    const float4* __restrict__ gF, const int* __restrict__ gI,
    uint32_t* __restrict__ Aout)
{
    constexpr int F_WLDS = CIN + 8;
    constexpr int NT = CIN / 8;
    __shared__ uint32_t sS[64 * S_WLDS];
    __shared__ uint32_t sF[32 * F_WLDS];
    __shared__ float4 sG[KNBR];
    __shared__ int    sJ[KNBR];
    __shared__ int    sB[KNBR];
    int n = blockIdx.x, t = threadIdx.x;
    int w = t >> 5, lane = t & 31;
    int g = lane >> 2, tg = lane & 3;

    if (t < KNBR) { sG[t] = gF[n*KNBR + t]; sB[t] = gI[n*KNBR + t]; sJ[t] = nbr[n*KNBR + t]; }
    for (int i = t; i < 64 * S_WLDS; i += 128) sS[i] = 0;
    __syncthreads();

    if (t < KNBR) {
        float4 gv = sG[t];
        if (gv.w != 0.f) {
            __nv_bfloat16* Sh = (__nv_bfloat16*)sS;
            int base = sB[t];
            float wx0 = (1.f - gv.x) * gv.w, wx1 = gv.x * gv.w;
            float wy0 = 1.f - gv.y, wy1 = gv.y;
            float wz0 = 1.f - gv.z, wz1 = gv.z;
            Sh[(base     ) * (2*S_WLDS) + t] = __float2bfloat16(wx0*wy0*wz0);
            Sh[(base +  1) * (2*S_WLDS) + t] = __float2bfloat16(wx0*wy0*wz1);
            Sh[(base +  4) * (2*S_WLDS) + t] = __float2bfloat16(wx0*wy1*wz0);
            Sh[(base +  5) * (2*S_WLDS) + t] = __float2bfloat16(wx0*wy1*wz1);
            Sh[(base + 16) * (2*S_WLDS) + t] = __float2bfloat16(wx1*wy0*wz0);
            Sh[(base + 17) * (2*S_WLDS) + t] = __float2bfloat16(wx1*wy0*wz1);
            Sh[(base + 20) * (2*S_WLDS) + t] = __float2bfloat16(wx1*wy1*wz0);
            Sh[(base + 21) * (2*S_WLDS) + t] = __float2bfloat16(wx1*wy1*wz1);
        }
    }

    for (int i = t; i < 32 * CIN; i += 128) {
        int kp = i / CIN, c = i - kp * CIN;
        uint32_t u0 = *(const unsigned short*)(featb + (size_t)sJ[2*kp    ] * CIN + c);
        uint32_t u1 = *(const unsigned short*)(featb + (size_t)sJ[2*kp + 1] * CIN + c);
        sF[kp * F_WLDS + c] = (u1 << 16) | u0;
    }
    __syncthreads();

    float acc[NT][4];
    #pragma unroll
    for (int nt = 0; nt < NT; nt++)
        #pragma unroll
        for (int q = 0; q < 4; q++) acc[nt][q] = 0.f;

    #pragma unroll
    for (int q = 0; q < 4; q++) {
        int r = w * 16 + g;
        uint32_t a0 = sS[(r    ) * S_WLDS + 8*q + tg    ];
        uint32_t a1 = sS[(r + 8) * S_WLDS + 8*q + tg    ];
        uint32_t a2 = sS[(r    ) * S_WLDS + 8*q + tg + 4];
        uint32_t a3 = sS[(r + 8) * S_WLDS + 8*q + tg + 4];
        #pragma unroll
        for (int nt = 0; nt < NT; nt++) {
            uint32_t b0 = sF[(8*q + tg    ) * F_WLDS + nt * 8 + g];
            uint32_t b1 = sF[(8*q + tg + 4) * F_WLDS + nt * 8 + g];
            asm volatile(
                "mma.sync.aligned.m16n8k16.row.col.f32.bf16.bf16.f32 "
                "{%0,%1,%2,%3},{%4,%5,%6,%7},{%8,%9},{%0,%1,%2,%3};"
                : "+f"(acc[nt][0]), "+f"(acc[nt][1]), "+f"(acc[nt][2]), "+f"(acc[nt][3])
                : "r"(a0), "r"(a1), "r"(a2), "r"(a3), "r"(b0), "r"(b1));
        }
    }

    uint32_t* out = Aout + (size_t)n * (32 * CIN);
    #pragma unroll
    for (int nt = 0; nt < NT; nt++) {
        #pragma unroll
        for (int h = 0; h < 2; h++) {
            int cell = w * 16 + g + h * 8;
            out[cell * (CIN/2) + nt * 4 + tg] = bf16x2(acc[nt][h*2+1], acc[nt][h*2+0]);
        }
    }
}

// ---------------- merged weight prep ----------------
#define N_WB2 (3072 * 64)
#define N_WB3 (2048 * 64)
#define N_WP4 (64 * 256)
__global__ void pack_all_kernel(
    const float* __restrict__ W2, const float* __restrict__ W3, const float* __restrict__ W4,
    uint32_t* __restrict__ Wb2, uint32_t* __restrict__ Wb3, float* __restrict__ Wp4)
{
    int idx = blockIdx.x * blockDim.x + threadIdx.x;
    if (idx < N_WB2) {
        int kp = idx >> 6, n = idx & 63;
        Wb2[idx] = bf16x2(W2[(size_t)(2*kp+1)*64 + n], W2[(size_t)(2*kp)*64 + n]);
    } else if (idx < N_WB2 + N_WB3) {
        int j = idx - N_WB2;
        int kp = j >> 6, n = j & 63;
        Wb3[j] = bf16x2(W3[(size_t)(2*kp+1)*64 + n], W3[(size_t)(2*kp)*64 + n]);
    } else if (idx < N_WB2 + N_WB3 + N_WP4) {
        int j = idx - N_WB2 - N_WB3;
        int c = j >> 8, col = j & 255;
        int cell = col >> 2, o = col & 3;
        Wp4[j] = (o < 3) ? W4[((size_t)cell * 64 + c) * 3 + o] : 0.f;
    }
}

// ---------------- pconv4 ----------------
__global__ __launch_bounds__(256) void pconv4_kernel(
    const float* __restrict__ X, const float* __restrict__ Wp, float* __restrict__ P)
{
    __shared__ float4 Xs[32][16];
    int t = threadIdx.x;
    int n0 = blockIdx.x * 32;
    for (int i = t; i < 512; i += 256) {
        int r = i >> 4, c4 = i & 15;
        Xs[r][c4] = *(const float4*)(X + (size_t)(n0 + r) * 64 + c4 * 4);
    }
    __syncthreads();

    float acc[32];
    #pragma unroll
    for (int r = 0; r < 32; r++) acc[r] = 0.f;
    #pragma unroll
    for (int c4 = 0; c4 < 16; c4++) {
        float w0 = Wp[(c4*4 + 0) * 256 + t];
        float w1 = Wp[(c4*4 + 1) * 256 + t];
        float w2 = Wp[(c4*4 + 2) * 256 + t];
        float w3 = Wp[(c4*4 + 3) * 256 + t];
        #pragma unroll
        for (int r = 0; r < 32; r++) {
            float4 xv = Xs[r][c4];
            acc[r] += xv.x*w0 + xv.y*w1 + xv.z*w2 + xv.w*w3;
        }
    }
    #pragma unroll
    for (int r = 0; r < 32; r++)
        P[(size_t)(n0 + r) * 256 + t] = acc[r];
}

// ---------------- conv4 gather + fused dense shortcut ----------------
__global__ __launch_bounds__(64) void conv4_kernel(
    const float* __restrict__ P, const int* __restrict__ nbr,
    const float4* __restrict__ gF, const int* __restrict__ gI,
    const float* __restrict__ bc4, const float* __restrict__ out3,
    const float* __restrict__ Wd4, const float* __restrict__ bd4,
    float* __restrict__ out)
{
    __shared__ float red[2][3];
    int n = blockIdx.x, t = threadIdx.x;
    float a0 = 0.f, a1 = 0.f, a2 = 0.f;
    {
        float x = out3[(size_t)n * 64 + t];
        a0 += x * Wd4[t*3 + 0];
        a1 += x * Wd4[t*3 + 1];
        a2 += x * Wd4[t*3 + 2];
    }
    float4 g = gF[n*KNBR + t];
    if (g.w != 0.f) {
        int j = nbr[n*KNBR + t];
        const float4* Pj = (const float4*)(P + (size_t)j * 256);
        int base = gI[n*KNBR + t];
        float wx0 = (1.f - g.x) * g.w, wx1 = g.x * g.w;
        float wy0 = 1.f - g.y, wy1 = g.y;
        float wz0 = 1.f - g.z, wz1 = g.z;
        float wq[8] = {wx0*wy0*wz0, wx0*wy0*wz1, wx0*wy1*wz0, wx0*wy1*wz1,
                       wx1*wy0*wz0, wx1*wy0*wz1, wx1*wy1*wz0, wx1*wy1*wz1};
        const int off[8] = {0, 1, 4, 5, 16, 17, 20, 21};
        #pragma unroll
        for (int q = 0; q < 8; q++) {
            float4 p = Pj[base + off[q]];
            a0 += wq[q] * p.x; a1 += wq[q] * p.y; a2 += wq[q] * p.z;
        }
    }
    #pragma unroll
    for (int s = 16; s > 0; s >>= 1) {
        a0 += __shfl_down_sync(0xffffffff, a0, s);
        a1 += __shfl_down_sync(0xffffffff, a1, s);
        a2 += __shfl_down_sync(0xffffffff, a2, s);
    }
    if ((t & 31) == 0) { red[t>>5][0] = a0; red[t>>5][1] = a1; red[t>>5][2] = a2; }
    __syncthreads();
    if (t < 3) out[n*3 + t] = red[0][t] + red[1][t] + bc4[t] + bd4[t];
}

// ---------------- bf16 tensor GEMM: M-tile 64, 250 CTAs ----------------
#define STAGES 4
#define A_WLDS 20
#define B_WLDS 72
#define A_WSTAGE (64*A_WLDS)
#define B_WSTAGE (16*B_WLDS)
#define GEMM_SMEM (STAGES*(A_WSTAGE + B_WSTAGE)*4)

template<int HAS_ADD, int HAS_RES, int RELU>
__global__ __launch_bounds__(128) void gemm_mma(
    const __nv_bfloat16* __restrict__ Ag, const uint32_t* __restrict__ Wb,
    const float* __restrict__ bias, const float* __restrict__ addv,
    const float* __restrict__ resv, float* __restrict__ out,
    __nv_bfloat16* __restrict__ outb, int K)
{
    extern __shared__ uint32_t sm[];
    uint32_t* sA = sm;
    uint32_t* sB = sm + STAGES * A_WSTAGE;
    int tid = threadIdx.x, w = tid >> 5, lane = tid & 31;
    int g = lane >> 2, tg = lane & 3;
    int m0 = blockIdx.x * 64;
    int NIT = K >> 5;
    uint32_t sAu = smem_u32(sA), sBu = smem_u32(sB);

    auto load_stage = [&](int s, int c) {
        uint32_t ab = sAu + (uint32_t)s * A_WSTAGE * 4;
        const __nv_bfloat16* as = Ag + (size_t)m0 * K + c * 32;
        #pragma unroll
        for (int r = 0; r < 2; r++) {
            int idx = r * 128 + tid;
            int row = idx >> 2, seg = idx & 3;
            cp16(ab + (row * A_WLDS + seg * 4) * 4, as + (size_t)row * K + seg * 8);
        }
        uint32_t bb = sBu + (uint32_t)s * B_WSTAGE * 4;
        const uint32_t* bs = Wb + (size_t)c * 16 * 64;
        #pragma unroll
        for (int r = 0; r < 2; r++) {
            int idx = r * 128 + tid;
            int kp = idx >> 4, seg = idx & 15;
            cp16(bb + (kp * B_WLDS + seg * 4) * 4, bs + kp * 64 + seg * 4);
        }
    };

    float acc[8][4];
    #pragma unroll
    for (int nt = 0; nt < 8; nt++)
        #pragma unroll
        for (int q = 0; q < 4; q++) acc[nt][q] = 0.f;

    #pragma unroll
    for (int s = 0; s < STAGES; s++) { load_stage(s, s); CP_COMMIT(); }

    for (int i = 0; i < NIT; i++) {
        asm volatile("cp.async.wait_group %0;" :: "n"(STAGES - 1));
        __syncthreads();
        const uint32_t* cA = sA + (i % STAGES) * A_WSTAGE;
        const uint32_t* cB = sB + (i % STAGES) * B_WSTAGE;
        #pragma unroll
        for (int q = 0; q < 2; q++) {
            int r = w * 16 + g;
            uint32_t a0 = cA[(r    ) * A_WLDS + 8*q + tg    ];
            uint32_t a1 = cA[(r + 8) * A_WLDS + 8*q + tg    ];
            uint32_t a2 = cA[(r    ) * A_WLDS + 8*q + tg + 4];
            uint32_t a3 = cA[(r + 8) * A_WLDS + 8*q + tg + 4];
            #pragma unroll
            for (int nt = 0; nt < 8; nt++) {
                uint32_t b0 = cB[(8*q + tg    ) * B_WLDS + nt * 8 + g];
                uint32_t b1 = cB[(8*q + tg + 4) * B_WLDS + nt * 8 + g];
                asm volatile(
                    "mma.sync.aligned.m16n8k16.row.col.f32.bf16.bf16.f32 "
                    "{%0,%1,%2,%3},{%4,%5,%6,%7},{%8,%9},{%0,%1,%2,%3};"
                    : "+f"(acc[nt][0]), "+f"(acc[nt][1]),
                      "+f"(acc[nt][2]), "+f"(acc[nt][3])
                    : "r"(a0), "r"(a1), "r"(a2), "r"(a3), "r"(b0), "r"(b1));
            }
        }
        __syncthreads();
        if (i + STAGES < NIT) load_stage(i % STAGES, i + STAGES);
        CP_COMMIT();
    }

    #pragma unroll
    for (int nt = 0; nt < 8; nt++) {
        #pragma unroll
        for (int h = 0; h < 2; h++) {
            int m = m0 + w * 16 + g + h * 8;
            int n0 = nt * 8 + 2 * tg;
            float lo = acc[nt][h*2+0], hi = acc[nt][h*2+1];
            float2 bb = *(const float2*)&bias[n0];
            lo += bb.x; hi += bb.y;
            if (HAS_ADD) {
                float2 v = *(const float2*)&addv[(size_t)m*64 + n0];
                lo += v.x; hi += v.y;
            }
            if (HAS_RES) {
                float2 v = *(const float2*)&resv[(size_t)m*64 + n0];
                lo += v.x; hi += v.y;
            }
            if (RELU) { lo = fmaxf(lo, 0.f); hi = fmaxf(hi, 0.f); }
            *(float2*)&out[(size_t)m*64 + n0] = make_float2(lo, hi);
            if (outb)
                *(uint32_t*)&outb[(size_t)m*64 + n0] = bf16x2(hi, lo);
        }
    }
}

// ---------------- dense GEMM ----------------
template<int CIN, int COUT, int RPT>
__global__ __launch_bounds__(COUT * (32 / RPT)) void dense_gemm(
    const float* __restrict__ X, const float* __restrict__ W,
    const float* __restrict__ b, float* __restrict__ Y,
    __nv_bfloat16* __restrict__ Yb, int ldY, int col0)
{
    constexpr int BD = COUT * (32 / RPT);
    __shared__ float Xs[32 * CIN];
    int t = threadIdx.x;
    int n0 = blockIdx.x * 32;
    for (int i = t; i < 32 * CIN; i += BD)
        Xs[i] = X[(size_t)n0 * CIN + i];
    __syncthreads();

    int o = t % COUT, rg = t / COUT;
    float acc[RPT];
    float bo = b[o];
    #pragma unroll
    for (int r = 0; r < RPT; r++) acc[r] = bo;
    #pragma unroll 4
    for (int c = 0; c < CIN; c++) {
        float wv = W[c * COUT + o];
        #pragma unroll
        for (int r = 0; r < RPT; r++)
            acc[r] += Xs[(rg * RPT + r) * CIN + c] * wv;
    }
    #pragma unroll
    for (int r = 0; r < RPT; r++) {
        size_t off = (size_t)(n0 + rg * RPT + r) * ldY + col0 + o;
        Y[off] = acc[r];
        if (Yb) Yb[off] = __float2bfloat16(acc[r]);
    }
}

// ---------------- launch ----------------
extern "C" void kernel_launch(void* const* d_in, const int* in_sizes, int n_in,
                              void* d_out, int out_size)
{
    const float* fluid_pos = (const float*)d_in[0];
    const float* wall_pos  = (const float*)d_in[1];
    const float* fluid_vel = (const float*)d_in[2];
    const float* wall_nv   = (const float*)d_in[3];
    const int*   nbr_wf    = (const int*)d_in[4];
    const void*  mask_wf   = d_in[5];
    const int*   nbr_ff    = (const int*)d_in[6];
    const void*  mask_ff   = d_in[7];
    const float* W_wall1 = (const float*)d_in[8];
    const float* b_wall1 = (const float*)d_in[9];
    const float* W_fluid1 = (const float*)d_in[10];
    const float* b_fluid1 = (const float*)d_in[11];
    const float* W_d1 = (const float*)d_in[12];
    const float* b_d1 = (const float*)d_in[13];
    const float* W_c2 = (const float*)d_in[14];
    const float* b_c2 = (const float*)d_in[15];
    const float* W_d2 = (const float*)d_in[16];
    const float* b_d2 = (const float*)d_in[17];
    const float* W_c3 = (const float*)d_in[18];
    const float* b_c3 = (const float*)d_in[19];
    const float* W_d3 = (const float*)d_in[20];
    const float* b_d3 = (const float*)d_in[21];
    const float* W_c4 = (const float*)d_in[22];
    const float* b_c4 = (const float*)d_in[23];
    const float* W_d4 = (const float*)d_in[24];
    const float* b_d4 = (const float*)d_in[25];

    void *pA, *pgFff, *pgIff, *pgFwf, *pgIwf, *pout1, *pout1b, *pout2, *pout2b,
         *pout3, *pdense, *pWb2, *pWb3, *pWp4;
    cudaGetSymbolAddress(&pA, g_A);
    cudaGetSymbolAddress(&pgFff, g_gF_ff);
    cudaGetSymbolAddress(&pgIff, g_gI_ff);
    cudaGetSymbolAddress(&pgFwf, g_gF_wf);
    cudaGetSymbolAddress(&pgIwf, g_gI_wf);
    cudaGetSymbolAddress(&pout1, g_out1);
    cudaGetSymbolAddress(&pout1b, g_out1b);
    cudaGetSymbolAddress(&pout2, g_out2);
    cudaGetSymbolAddress(&pout2b, g_out2b);
    cudaGetSymbolAddress(&pout3, g_out3);
    cudaGetSymbolAddress(&pdense, g_dense);
    cudaGetSymbolAddress(&pWb2, g_Wb2);
    cudaGetSymbolAddress(&pWb3, g_Wb3);
    cudaGetSymbolAddress(&pWp4, g_Wp4);
    void*   A     = pA;
    float4* gFff  = (float4*)pgFff;
    int*    gIff  = (int*)pgIff;
    float4* gFwf  = (float4*)pgFwf;
    int*    gIwf  = (int*)pgIwf;
    float*  out1  = (float*)pout1;
    __nv_bfloat16* out1b = (__nv_bfloat16*)pout1b;
    float*  out2  = (float*)pout2;
    __nv_bfloat16* out2b = (__nv_bfloat16*)pout2b;
    float*  out3  = (float*)pout3;
    float*  dense = (float*)pdense;
    uint32_t* Wb2 = (uint32_t*)pWb2;
    uint32_t* Wb3 = (uint32_t*)pWb3;
    float*  Wp4   = (float*)pWp4;

    cudaFuncSetAttribute(gemm_mma<1,0,1>, cudaFuncAttributeMaxDynamicSharedMemorySize, GEMM_SMEM);
    cudaFuncSetAttribute(gemm_mma<1,1,1>, cudaFuncAttributeMaxDynamicSharedMemorySize, GEMM_SMEM);

    const int tot = NF * KNBR;
    detect_mask_kernel<<<1, 1024>>>((const unsigned int*)mask_wf);
    geom2_kernel<<<(2*tot + 255)/256, 256>>>(fluid_pos, wall_pos,
                                             nbr_ff, mask_ff, gFff, gIff,
                                             nbr_wf, mask_wf, gFwf, gIwf);
    pack_all_kernel<<<(N_WB2 + N_WB3 + N_WP4 + 255)/256, 256>>>(W_c2, W_c3, W_c4, Wb2, Wb3, Wp4);

    // layer 1 (split convs — measured faster than merged)
    conv1_kernel<<<NF/4, 256>>>(wall_nv,   nbr_wf, gFwf, gIwf, W_wall1,  b_wall1,  out1, out1b, 0);
    conv1_kernel<<<NF/4, 256>>>(fluid_vel, nbr_ff, gFff, gIff, W_fluid1, b_fluid1, out1, out1b, 32);
    dense_gemm<3, 32, 4><<<NF/32, 256>>>(fluid_vel, W_d1, b_d1, out1, out1b, 96, 64);

    // layer 2
    dense_gemm<96, 64, 8><<<NF/32, 256>>>(out1, W_d2, b_d2, dense, nullptr, 64, 0);
    cellgemm_kernel<96><<<NF, 128>>>(out1b, nbr_ff, gFff, gIff, (uint32_t*)A);
    gemm_mma<1, 0, 1><<<NF/64, 128, GEMM_SMEM>>>((const __nv_bfloat16*)A, Wb2, b_c2, dense,
                                                 nullptr, out2, out2b, 6144);

    // layer 3
    dense_gemm<64, 64, 8><<<NF/32, 256>>>(out2, W_d3, b_d3, dense, nullptr, 64, 0);
    cellgemm_kernel<64><<<NF, 128>>>(out2b, nbr_ff, gFff, gIff, (uint32_t*)A);
    gemm_mma<1, 1, 1><<<NF/64, 128, GEMM_SMEM>>>((const __nv_bfloat16*)A, Wb3, b_c3, dense,
                                                 out2, out3, nullptr, 4096);

    // layer 4
    pconv4_kernel<<<NF/32, 256>>>(out3, Wp4, (float*)A);
    conv4_kernel<<<NF, 64>>>((const float*)A, nbr_ff, gFff, gIff, b_c4,
                             out3, W_d4, b_d4, (float*)d_out);
}

// round 14
// speedup vs baseline: 1.0448x; 1.0448x over previous
#include <cuda_runtime.h>
#include <cuda_bf16.h>
#include <cstdint>
#include <cstddef>

#define NF   16000
#define KNBR 64
#define RADIUS_F ((float)(0.5*6.0*1.5*0.025))

// ---------------- scratch (device globals; no allocation APIs) ----------------
__device__ float  g_A[(size_t)NF * 64 * 96];   // bf16 A for layers 2/3; fp32 P for layer 4
__device__ float4 g_gF_ff[NF * KNBR];
__device__ int    g_gI_ff[NF * KNBR];
__device__ float4 g_gF_wf[NF * KNBR];
__device__ int    g_gI_wf[NF * KNBR];
__device__ float  g_out1[NF * 96];
__device__ __nv_bfloat16 g_out1b[NF * 96];     // bf16 mirror of out1 (cellgemm gather)
__device__ float  g_out2[NF * 64];
__device__ __nv_bfloat16 g_out2b[NF * 64];     // bf16 mirror of out2
__device__ float  g_out3[NF * 64];
__device__ float  g_dense[NF * 64];
__device__ uint32_t g_Wb2[3072 * 64];          // W_c2 packed bf16x2, [kp][n]
__device__ uint32_t g_Wb3[2048 * 64];          // W_c3 packed bf16x2
__device__ float  g_Wp4[64 * 256];             // W_c4 re-laid [c][cell*4+o], pad o=3 -> 0
__device__ int    g_mask_u8;

// ---------------- helpers ----------------
__device__ __forceinline__ uint32_t smem_u32(const void* p) {
    uint32_t a;
    asm("{ .reg .u64 t; cvta.to.shared.u64 t, %1; cvt.u32.u64 %0, t; }" : "=r"(a) : "l"(p));
    return a;
}
__device__ __forceinline__ void cp16(uint32_t dst, const void* src) {
    asm volatile("cp.async.cg.shared.global [%0], [%1], 16;" :: "r"(dst), "l"(src));
}
#define CP_COMMIT() asm volatile("cp.async.commit_group;" ::: "memory")
__device__ __forceinline__ uint32_t bf16x2(float hi, float lo) {
    uint32_t r;
    asm("cvt.rn.bf16x2.f32 %0, %1, %2;" : "=r"(r) : "f"(hi), "f"(lo));
    return r;
}
__device__ __forceinline__ float fast_sqrt_pos(float m) {   // m > 0
    return m * rsqrtf(m);
}

// ---------------- mask dtype detector ----------------
__global__ void detect_mask_kernel(const unsigned int* __restrict__ m)
{
    __shared__ int s;
    if (threadIdx.x == 0) s = 0;
    __syncthreads();
    int bad = 0;
    for (int i = threadIdx.x; i < 16384; i += blockDim.x)
        if (m[i] > 1u) { bad = 1; break; }
    if (bad) atomicOr(&s, 1);
    __syncthreads();
    if (threadIdx.x == 0) g_mask_u8 = s;
}

// ---------------- geometry (both neighbor sets, fast math) ----------------
static __device__ __forceinline__ float sgnf(float v) {
    return (v > 0.f) ? 1.f : ((v < 0.f) ? -1.f : 0.f);
}
__device__ __forceinline__ void gridmap(float u, int& i0, float& f) {
    float cc = (u * 0.5f + 0.5f) * 3.f;
    cc = fminf(fmaxf(cc, 0.f), 3.f);
    float fi = floorf(cc);
    fi = fminf(fi, 2.f);
    f = cc - fi;
    i0 = (int)fi;
}

__global__ void geom2_kernel(
    const float* __restrict__ fluid_pos, const float* __restrict__ wall_pos,
    const int* __restrict__ nbr_ff, const void* __restrict__ mask_ff,
    float4* __restrict__ gFff, int* __restrict__ gIff,
    const int* __restrict__ nbr_wf, const void* __restrict__ mask_wf,
    float4* __restrict__ gFwf, int* __restrict__ gIwf)
{
    int gidx = blockIdx.x * blockDim.x + threadIdx.x;
    if (gidx >= 2 * NF * KNBR) return;
    int which = gidx >= NF * KNBR;                 // uniform per block
    int idx = which ? gidx - NF * KNBR : gidx;
    const float* pin = which ? wall_pos : fluid_pos;
    const int*   nbr = which ? nbr_wf   : nbr_ff;
    const void*  mask = which ? mask_wf : mask_ff;
    float4* gF = which ? gFwf : gFff;
    int*    gI = which ? gIwf : gIff;

    int mv = g_mask_u8 ? (int)((const unsigned char*)mask)[idx]
                       : ((const int*)mask)[idx];
    if (mv == 0) { gF[idx] = make_float4(0.f, 0.f, 0.f, 0.f); gI[idx] = 0; return; }
    int n = idx >> 6;
    int j = nbr[idx];
    float x = (pin[j*3+0] - fluid_pos[n*3+0]) * (1.f / RADIUS_F);
    float y = (pin[j*3+1] - fluid_pos[n*3+1]) * (1.f / RADIUS_F);
    float z = (pin[j*3+2] - fluid_pos[n*3+2]) * (1.f / RADIUS_F);
    float sq = x*x + y*y + z*z;
    float t1 = 1.f - sq;
    float win = fminf(fmaxf(t1*t1*t1, 0.f), 1.f);

    const float eps = 1e-12f;
    float norm = fast_sqrt_pos(fmaxf(sq, eps));
    float rho  = fast_sqrt_pos(fmaxf(x*x + y*y, eps));
    bool  top  = (1.25f*z*z > x*x + y*y);
    float st_arg = __fdividef(3.f*norm, norm + fabsf(z));
    float s_top = fast_sqrt_pos(st_arg);
    float inv_rho_n = __fdividef(norm, rho);
    float xs = top ? x*s_top : x*inv_rho_n;
    float ys = top ? y*s_top : y*inv_rho_n;
    float zs = top ? sgnf(z)*norm : 1.5f*z;
    if (sq < eps) { xs = 0.f; ys = 0.f; zs = 0.f; }
    float rxy = fast_sqrt_pos(fmaxf(xs*xs + ys*ys, eps));
    bool use_x = fabsf(ys) <= fabsf(xs);
    float ddx = (use_x  && fabsf(xs) > eps) ? xs : 1.f;
    float ddy = (!use_x && fabsf(ys) > eps) ? ys : 1.f;
    const float c4 = 1.27323954473516276487f;  // 4/pi
    float xc = use_x ? sgnf(xs)*rxy : sgnf(ys)*rxy*c4*atanf(__fdividef(xs, ddy));
    float yc = use_x ? sgnf(xs)*rxy*c4*atanf(__fdividef(ys, ddx)) : sgnf(ys)*rxy;
    if (xs*xs + ys*ys < eps) { xc = 0.f; yc = 0.f; }

    int ix, iy, iz; float fx, fy, fz;
    gridmap(xc, ix, fx); gridmap(yc, iy, fy); gridmap(zs, iz, fz);
    gF[idx] = make_float4(fx, fy, fz, win);
    gI[idx] = (ix*4 + iy)*4 + iz;
}

// ---------------- layer-1 cconv (cin=3, cout=32), W staged in smem (split, proven) --------
__global__ __launch_bounds__(256) void conv1_kernel(
    const float* __restrict__ feat, const int* __restrict__ nbr,
    const float4* __restrict__ gF, const int* __restrict__ gI,
    const float* __restrict__ W, const float* __restrict__ b,
    float* __restrict__ out1, __nv_bfloat16* __restrict__ out1b, int col0)
{
    __shared__ float A[4][192];
    __shared__ float sW[192 * 32];
    __shared__ float red[256];
    int t = threadIdx.x;
    int p = t >> 6, tl = t & 63;
    int n = blockIdx.x * 4 + p;
    float* Ap = A[p];
    Ap[tl] = 0.f; Ap[tl + 64] = 0.f; Ap[tl + 128] = 0.f;
    #pragma unroll
    for (int i = 0; i < 24; i++) sW[i * 256 + t] = W[i * 256 + t];
    __syncthreads();

    int idx = n * KNBR + tl;
    float4 g = gF[idx];
    if (g.w != 0.f) {
        int j = nbr[idx];
        float f0 = feat[j*3+0]*g.w, f1 = feat[j*3+1]*g.w, f2 = feat[j*3+2]*g.w;
        int base = gI[idx];
        float wx[2] = {1.f - g.x, g.x};
        float wy[2] = {1.f - g.y, g.y};
        float wz[2] = {1.f - g.z, g.z};
        #pragma unroll
        for (int cx = 0; cx < 2; cx++)
        #pragma unroll
        for (int cy = 0; cy < 2; cy++)
        #pragma unroll
        for (int cz = 0; cz < 2; cz++) {
            float wc = wx[cx]*wy[cy]*wz[cz];
            int cell = base + cx*16 + cy*4 + cz;
            atomicAdd(&Ap[cell*3+0], wc*f0);
            atomicAdd(&Ap[cell*3+1], wc*f1);
            atomicAdd(&Ap[cell*3+2], wc*f2);
        }
    }
    __syncthreads();

    int o = tl & 31, h = tl >> 5;
    float acc = 0.f;
    #pragma unroll 8
    for (int i = h*96; i < h*96 + 96; i++)
        acc += Ap[i] * sW[i*32 + o];
    red[t] = acc;
    __syncthreads();
    if (tl < 32) {
        float v = red[p*64 + tl] + red[p*64 + tl + 32] + b[o];
        v = fmaxf(v, 0.f);
        out1 [n*96 + col0 + tl] = v;
        out1b[n*96 + col0 + tl] = __float2bfloat16(v);
    }
}

// ---------------- cellgemm: A[n] = S[n] @ F[n] on tensor cores (layers 2/3) ----------------
#define S_WLDS 36
template<int CIN>
__global__ __launch_bounds__(128) void cellgemm_kernel(
    const __nv_bfloat16* __restrict__ featb, const int* __restrict__ nbr,
    const float4* __restrict__ gF, const int* __restrict__ gI,
    uint32_t* __restrict__ Aout)
{
    constexpr int F_WLDS = CIN + 8;
    constexpr int NT = CIN / 8;
    __shared__ uint32_t sS[64 * S_WLDS];
    __shared__ uint32_t sF[32 * F_WLDS];
    __shared__ float4 sG[KNBR];
    __shared__ int    sJ[KNBR];
    __shared__ int    sB[KNBR];
    int n = blockIdx.x, t = threadIdx.x;
    int w = t >> 5, lane = t & 31;
    int g = lane >> 2, tg = lane & 3;

    if (t < KNBR) { sG[t] = gF[n*KNBR + t]; sB[t] = gI[n*KNBR + t]; sJ[t] = nbr[n*KNBR + t]; }
    for (int i = t; i < 64 * S_WLDS; i += 128) sS[i] = 0;
    __syncthreads();

    if (t < KNBR) {
        float4 gv = sG[t];
        if (gv.w != 0.f) {
            __nv_bfloat16* Sh = (__nv_bfloat16*)sS;
            int base = sB[t];
            float wx0 = (1.f - gv.x) * gv.w, wx1 = gv.x * gv.w;
            float wy0 = 1.f - gv.y, wy1 = gv.y;
            float wz0 = 1.f - gv.z, wz1 = gv.z;
            Sh[(base     ) * (2*S_WLDS) + t] = __float2bfloat16(wx0*wy0*wz0);
            Sh[(base +  1) * (2*S_WLDS) + t] = __float2bfloat16(wx0*wy0*wz1);
            Sh[(base +  4) * (2*S_WLDS) + t] = __float2bfloat16(wx0*wy1*wz0);
            Sh[(base +  5) * (2*S_WLDS) + t] = __float2bfloat16(wx0*wy1*wz1);
            Sh[(base + 16) * (2*S_WLDS) + t] = __float2bfloat16(wx1*wy0*wz0);
            Sh[(base + 17) * (2*S_WLDS) + t] = __float2bfloat16(wx1*wy0*wz1);
            Sh[(base + 20) * (2*S_WLDS) + t] = __float2bfloat16(wx1*wy1*wz0);
            Sh[(base + 21) * (2*S_WLDS) + t] = __float2bfloat16(wx1*wy1*wz1);
        }
    }

    for (int i = t; i < 32 * CIN; i += 128) {
        int kp = i / CIN, c = i - kp * CIN;
        uint32_t u0 = *(const unsigned short*)(featb + (size_t)sJ[2*kp    ] * CIN + c);
        uint32_t u1 = *(const unsigned short*)(featb + (size_t)sJ[2*kp + 1] * CIN + c);
        sF[kp * F_WLDS + c] = (u1 << 16) | u0;
    }
    __syncthreads();

    float acc[NT][4];
    #pragma unroll
    for (int nt = 0; nt < NT; nt++)
        #pragma unroll
        for (int q = 0; q < 4; q++) acc[nt][q] = 0.f;

    #pragma unroll
    for (int q = 0; q < 4; q++) {
        int r = w * 16 + g;
        uint32_t a0 = sS[(r    ) * S_WLDS + 8*q + tg    ];
        uint32_t a1 = sS[(r + 8) * S_WLDS + 8*q + tg    ];
        uint32_t a2 = sS[(r    ) * S_WLDS + 8*q + tg + 4];
        uint32_t a3 = sS[(r + 8) * S_WLDS + 8*q + tg + 4];
        #pragma unroll
        for (int nt = 0; nt < NT; nt++) {
            uint32_t b0 = sF[(8*q + tg    ) * F_WLDS + nt * 8 + g];
            uint32_t b1 = sF[(8*q + tg + 4) * F_WLDS + nt * 8 + g];
            asm volatile(
                "mma.sync.aligned.m16n8k16.row.col.f32.bf16.bf16.f32 "
                "{%0,%1,%2,%3},{%4,%5,%6,%7},{%8,%9},{%0,%1,%2,%3};"
                : "+f"(acc[nt][0]), "+f"(acc[nt][1]), "+f"(acc[nt][2]), "+f"(acc[nt][3])
                : "r"(a0), "r"(a1), "r"(a2), "r"(a3), "r"(b0), "r"(b1));
        }
    }

    uint32_t* out = Aout + (size_t)n * (32 * CIN);
    #pragma unroll
    for (int nt = 0; nt < NT; nt++) {
        #pragma unroll
        for (int h = 0; h < 2; h++) {
            int cell = w * 16 + g + h * 8;
            out[cell * (CIN/2) + nt * 4 + tg] = bf16x2(acc[nt][h*2+1], acc[nt][h*2+0]);
        }
    }
}

// ---------------- merged weight prep ----------------
#define N_WB2 (3072 * 64)
#define N_WB3 (2048 * 64)
#define N_WP4 (64 * 256)
__global__ void pack_all_kernel(
    const float* __restrict__ W2, const float* __restrict__ W3, const float* __restrict__ W4,
    uint32_t* __restrict__ Wb2, uint32_t* __restrict__ Wb3, float* __restrict__ Wp4)
{
    int idx = blockIdx.x * blockDim.x + threadIdx.x;
    if (idx < N_WB2) {
        int kp = idx >> 6, n = idx & 63;
        Wb2[idx] = bf16x2(W2[(size_t)(2*kp+1)*64 + n], W2[(size_t)(2*kp)*64 + n]);
    } else if (idx < N_WB2 + N_WB3) {
        int j = idx - N_WB2;
        int kp = j >> 6, n = j & 63;
        Wb3[j] = bf16x2(W3[(size_t)(2*kp+1)*64 + n], W3[(size_t)(2*kp)*64 + n]);
    } else if (idx < N_WB2 + N_WB3 + N_WP4) {
        int j = idx - N_WB2 - N_WB3;
        int c = j >> 8, col = j & 255;
        int cell = col >> 2, o = col & 3;
        Wp4[j] = (o < 3) ? W4[((size_t)cell * 64 + c) * 3 + o] : 0.f;
    }
}

// ---------------- pconv4 ----------------
__global__ __launch_bounds__(256) void pconv4_kernel(
    const float* __restrict__ X, const float* __restrict__ Wp, float* __restrict__ P)
{
    __shared__ float4 Xs[32][16];
    int t = threadIdx.x;
    int n0 = blockIdx.x * 32;
    for (int i = t; i < 512; i += 256) {
        int r = i >> 4, c4 = i & 15;
        Xs[r][c4] = *(const float4*)(X + (size_t)(n0 + r) * 64 + c4 * 4);
    }
    __syncthreads();

    float acc[32];
    #pragma unroll
    for (int r = 0; r < 32; r++) acc[r] = 0.f;
    #pragma unroll
    for (int c4 = 0; c4 < 16; c4++) {
        float w0 = Wp[(c4*4 + 0) * 256 + t];
        float w1 = Wp[(c4*4 + 1) * 256 + t];
        float w2 = Wp[(c4*4 + 2) * 256 + t];
        float w3 = Wp[(c4*4 + 3) * 256 + t];
        #pragma unroll
        for (int r = 0; r < 32; r++) {
            float4 xv = Xs[r][c4];
            acc[r] += xv.x*w0 + xv.y*w1 + xv.z*w2 + xv.w*w3;
        }
    }
    #pragma unroll
    for (int r = 0; r < 32; r++)
        P[(size_t)(n0 + r) * 256 + t] = acc[r];
}

// ---------------- conv4 gather + fused dense shortcut ----------------
__global__ __launch_bounds__(64) void conv4_kernel(
    const float* __restrict__ P, const int* __restrict__ nbr,
    const float4* __restrict__ gF, const int* __restrict__ gI,
    const float* __restrict__ bc4, const float* __restrict__ out3,
    const float* __restrict__ Wd4, const float* __restrict__ bd4,
    float* __restrict__ out)
{
    __shared__ float red[2][3];
    int n = blockIdx.x, t = threadIdx.x;
    float a0 = 0.f, a1 = 0.f, a2 = 0.f;
    {
        float x = out3[(size_t)n * 64 + t];
        a0 += x * Wd4[t*3 + 0];
        a1 += x * Wd4[t*3 + 1];
        a2 += x * Wd4[t*3 + 2];
    }
    float4 g = gF[n*KNBR + t];
    if (g.w != 0.f) {
        int j = nbr[n*KNBR + t];
        const float4* Pj = (const float4*)(P + (size_t)j * 256);
        int base = gI[n*KNBR + t];
        float wx0 = (1.f - g.x) * g.w, wx1 = g.x * g.w;
        float wy0 = 1.f - g.y, wy1 = g.y;
        float wz0 = 1.f - g.z, wz1 = g.z;
        float wq[8] = {wx0*wy0*wz0, wx0*wy0*wz1, wx0*wy1*wz0, wx0*wy1*wz1,
                       wx1*wy0*wz0, wx1*wy0*wz1, wx1*wy1*wz0, wx1*wy1*wz1};
        const int off[8] = {0, 1, 4, 5, 16, 17, 20, 21};
        #pragma unroll
        for (int q = 0; q < 8; q++) {
            float4 p = Pj[base + off[q]];
            a0 += wq[q] * p.x; a1 += wq[q] * p.y; a2 += wq[q] * p.z;
        }
    }
    #pragma unroll
    for (int s = 16; s > 0; s >>= 1) {
        a0 += __shfl_down_sync(0xffffffff, a0, s);
        a1 += __shfl_down_sync(0xffffffff, a1, s);
        a2 += __shfl_down_sync(0xffffffff, a2, s);
    }
    if ((t & 31) == 0) { red[t>>5][0] = a0; red[t>>5][1] = a1; red[t>>5][2] = a2; }
    __syncthreads();
    if (t < 3) out[n*3 + t] = red[0][t] + red[1][t] + bc4[t] + bd4[t];
}

// ---------------- bf16 tensor GEMM: M-tile 128 (measured best) ----------------
#define STAGES 4
#define A_WLDS 20
#define B_WLDS 72
#define A_WSTAGE (128*A_WLDS)
#define B_WSTAGE (16*B_WLDS)
#define GEMM_SMEM (STAGES*(A_WSTAGE + B_WSTAGE)*4)

template<int HAS_ADD, int HAS_RES, int RELU>
__global__ __launch_bounds__(128) void gemm_mma(
    const __nv_bfloat16* __restrict__ Ag, const uint32_t* __restrict__ Wb,
    const float* __restrict__ bias, const float* __restrict__ addv,
    const float* __restrict__ resv, float* __restrict__ out,
    __nv_bfloat16* __restrict__ outb, int K)
{
    extern __shared__ uint32_t sm[];
    uint32_t* sA = sm;
    uint32_t* sB = sm + STAGES * A_WSTAGE;
    int tid = threadIdx.x, w = tid >> 5, lane = tid & 31;
    int g = lane >> 2, tg = lane & 3;
    int m0 = blockIdx.x * 128;
    int NIT = K >> 5;
    uint32_t sAu = smem_u32(sA), sBu = smem_u32(sB);

    auto load_stage = [&](int s, int c) {
        uint32_t ab = sAu + (uint32_t)s * A_WSTAGE * 4;
        const __nv_bfloat16* as = Ag + (size_t)m0 * K + c * 32;
        #pragma unroll
        for (int r = 0; r < 4; r++) {
            int idx = r * 128 + tid;
            int row = idx >> 2, seg = idx & 3;
            cp16(ab + (row * A_WLDS + seg * 4) * 4, as + (size_t)row * K + seg * 8);
        }
        uint32_t bb = sBu + (uint32_t)s * B_WSTAGE * 4;
        const uint32_t* bs = Wb + (size_t)c * 16 * 64;
        #pragma unroll
        for (int r = 0; r < 2; r++) {
            int idx = r * 128 + tid;
            int kp = idx >> 4, seg = idx & 15;
            cp16(bb + (kp * B_WLDS + seg * 4) * 4, bs + kp * 64 + seg * 4);
        }
    };

    float acc[2][8][4];
    #pragma unroll
    for (int mt = 0; mt < 2; mt++)
        #pragma unroll
        for (int nt = 0; nt < 8; nt++)
            #pragma unroll
            for (int q = 0; q < 4; q++) acc[mt][nt][q] = 0.f;

    #pragma unroll
    for (int s = 0; s < STAGES; s++) { load_stage(s, s); CP_COMMIT(); }

    for (int i = 0; i < NIT; i++) {
        asm volatile("cp.async.wait_group %0;" :: "n"(STAGES - 1));
        __syncthreads();
        const uint32_t* cA = sA + (i % STAGES) * A_WSTAGE;
        const uint32_t* cB = sB + (i % STAGES) * B_WSTAGE;
        #pragma unroll
        for (int q = 0; q < 2; q++) {
            uint32_t a[2][4], b[8][2];
            #pragma unroll
            for (int mt = 0; mt < 2; mt++) {
                int r = w * 32 + mt * 16 + g;
                a[mt][0] = cA[(r    ) * A_WLDS + 8*q + tg    ];
                a[mt][1] = cA[(r + 8) * A_WLDS + 8*q + tg    ];
                a[mt][2] = cA[(r    ) * A_WLDS + 8*q + tg + 4];
                a[mt][3] = cA[(r + 8) * A_WLDS + 8*q + tg + 4];
            }
            #pragma unroll
            for (int nt = 0; nt < 8; nt++) {
                b[nt][0] = cB[(8*q + tg    ) * B_WLDS + nt * 8 + g];
                b[nt][1] = cB[(8*q + tg + 4) * B_WLDS + nt * 8 + g];
            }
            #pragma unroll
            for (int mt = 0; mt < 2; mt++)
                #pragma unroll
                for (int nt = 0; nt < 8; nt++)
                    asm volatile(
                        "mma.sync.aligned.m16n8k16.row.col.f32.bf16.bf16.f32 "
                        "{%0,%1,%2,%3},{%4,%5,%6,%7},{%8,%9},{%0,%1,%2,%3};"
                        : "+f"(acc[mt][nt][0]), "+f"(acc[mt][nt][1]),
                          "+f"(acc[mt][nt][2]), "+f"(acc[mt][nt][3])
                        : "r"(a[mt][0]), "r"(a[mt][1]), "r"(a[mt][2]), "r"(a[mt][3]),
                          "r"(b[nt][0]), "r"(b[nt][1]));
        }
        __syncthreads();
        if (i + STAGES < NIT) load_stage(i % STAGES, i + STAGES);
        CP_COMMIT();
    }

    #pragma unroll
    for (int mt = 0; mt < 2; mt++) {
        #pragma unroll
        for (int nt = 0; nt < 8; nt++) {
            #pragma unroll
            for (int h = 0; h < 2; h++) {
                int m = m0 + w * 32 + mt * 16 + g + h * 8;
                int n0 = nt * 8 + 2 * tg;
                float lo = acc[mt][nt][h*2+0], hi = acc[mt][nt][h*2+1];
                float2 bb = *(const float2*)&bias[n0];
                lo += bb.x; hi += bb.y;
                if (HAS_ADD) {
                    float2 v = *(const float2*)&addv[(size_t)m*64 + n0];
                    lo += v.x; hi += v.y;
                }
                if (HAS_RES) {
                    float2 v = *(const float2*)&resv[(size_t)m*64 + n0];
                    lo += v.x; hi += v.y;
                }
                if (RELU) { lo = fmaxf(lo, 0.f); hi = fmaxf(hi, 0.f); }
                *(float2*)&out[(size_t)m*64 + n0] = make_float2(lo, hi);
                if (outb)
                    *(uint32_t*)&outb[(size_t)m*64 + n0] = bf16x2(hi, lo);
            }
        }
    }
}

// ---------------- dense GEMM ----------------
template<int CIN, int COUT, int RPT>
__global__ __launch_bounds__(COUT * (32 / RPT)) void dense_gemm(
    const float* __restrict__ X, const float* __restrict__ W,
    const float* __restrict__ b, float* __restrict__ Y,
    __nv_bfloat16* __restrict__ Yb, int ldY, int col0)
{
    constexpr int BD = COUT * (32 / RPT);
    __shared__ float Xs[32 * CIN];
    int t = threadIdx.x;
    int n0 = blockIdx.x * 32;
    for (int i = t; i < 32 * CIN; i += BD)
        Xs[i] = X[(size_t)n0 * CIN + i];
    __syncthreads();

    int o = t % COUT, rg = t / COUT;
    float acc[RPT];
    float bo = b[o];
    #pragma unroll
    for (int r = 0; r < RPT; r++) acc[r] = bo;
    #pragma unroll 4
    for (int c = 0; c < CIN; c++) {
        float wv = W[c * COUT + o];
        #pragma unroll
        for (int r = 0; r < RPT; r++)
            acc[r] += Xs[(rg * RPT + r) * CIN + c] * wv;
    }
    #pragma unroll
    for (int r = 0; r < RPT; r++) {
        size_t off = (size_t)(n0 + rg * RPT + r) * ldY + col0 + o;
        Y[off] = acc[r];
        if (Yb) Yb[off] = __float2bfloat16(acc[r]);
    }
}

// ---------------- launch ----------------
extern "C" void kernel_launch(void* const* d_in, const int* in_sizes, int n_in,
                              void* d_out, int out_size)
{
    const float* fluid_pos = (const float*)d_in[0];
    const float* wall_pos  = (const float*)d_in[1];
    const float* fluid_vel = (const float*)d_in[2];
    const float* wall_nv   = (const float*)d_in[3];
    const int*   nbr_wf    = (const int*)d_in[4];
    const void*  mask_wf   = d_in[5];
    const int*   nbr_ff    = (const int*)d_in[6];
    const void*  mask_ff   = d_in[7];
    const float* W_wall1 = (const float*)d_in[8];
    const float* b_wall1 = (const float*)d_in[9];
    const float* W_fluid1 = (const float*)d_in[10];
    const float* b_fluid1 = (const float*)d_in[11];
    const float* W_d1 = (const float*)d_in[12];
    const float* b_d1 = (const float*)d_in[13];
    const float* W_c2 = (const float*)d_in[14];
    const float* b_c2 = (const float*)d_in[15];
    const float* W_d2 = (const float*)d_in[16];
    const float* b_d2 = (const float*)d_in[17];
    const float* W_c3 = (const float*)d_in[18];
    const float* b_c3 = (const float*)d_in[19];
    const float* W_d3 = (const float*)d_in[20];
    const float* b_d3 = (const float*)d_in[21];
    const float* W_c4 = (const float*)d_in[22];
    const float* b_c4 = (const float*)d_in[23];
    const float* W_d4 = (const float*)d_in[24];
    const float* b_d4 = (const float*)d_in[25];

    void *pA, *pgFff, *pgIff, *pgFwf, *pgIwf, *pout1, *pout1b, *pout2, *pout2b,
         *pout3, *pdense, *pWb2, *pWb3, *pWp4;
    cudaGetSymbolAddress(&pA, g_A);
    cudaGetSymbolAddress(&pgFff, g_gF_ff);
    cudaGetSymbolAddress(&pgIff, g_gI_ff);
    cudaGetSymbolAddress(&pgFwf, g_gF_wf);
    cudaGetSymbolAddress(&pgIwf, g_gI_wf);
    cudaGetSymbolAddress(&pout1, g_out1);
    cudaGetSymbolAddress(&pout1b, g_out1b);
    cudaGetSymbolAddress(&pout2, g_out2);
    cudaGetSymbolAddress(&pout2b, g_out2b);
    cudaGetSymbolAddress(&pout3, g_out3);
    cudaGetSymbolAddress(&pdense, g_dense);
    cudaGetSymbolAddress(&pWb2, g_Wb2);
    cudaGetSymbolAddress(&pWb3, g_Wb3);
    cudaGetSymbolAddress(&pWp4, g_Wp4);
    void*   A     = pA;
    float4* gFff  = (float4*)pgFff;
    int*    gIff  = (int*)pgIff;
    float4* gFwf  = (float4*)pgFwf;
    int*    gIwf  = (int*)pgIwf;
    float*  out1  = (float*)pout1;
    __nv_bfloat16* out1b = (__nv_bfloat16*)pout1b;
    float*  out2  = (float*)pout2;
    __nv_bfloat16* out2b = (__nv_bfloat16*)pout2b;
    float*  out3  = (float*)pout3;
    float*  dense = (float*)pdense;
    uint32_t* Wb2 = (uint32_t*)pWb2;
    uint32_t* Wb3 = (uint32_t*)pWb3;
    float*  Wp4   = (float*)pWp4;

    cudaFuncSetAttribute(gemm_mma<1,0,1>, cudaFuncAttributeMaxDynamicSharedMemorySize, GEMM_SMEM);
    cudaFuncSetAttribute(gemm_mma<1,1,1>, cudaFuncAttributeMaxDynamicSharedMemorySize, GEMM_SMEM);

    const int tot = NF * KNBR;
    detect_mask_kernel<<<1, 1024>>>((const unsigned int*)mask_wf);
    geom2_kernel<<<(2*tot + 255)/256, 256>>>(fluid_pos, wall_pos,
                                             nbr_ff, mask_ff, gFff, gIff,
                                             nbr_wf, mask_wf, gFwf, gIwf);
    pack_all_kernel<<<(N_WB2 + N_WB3 + N_WP4 + 255)/256, 256>>>(W_c2, W_c3, W_c4, Wb2, Wb3, Wp4);

    // layer 1 (split convs — measured faster than merged)
    conv1_kernel<<<NF/4, 256>>>(wall_nv,   nbr_wf, gFwf, gIwf, W_wall1,  b_wall1,  out1, out1b, 0);
    conv1_kernel<<<NF/4, 256>>>(fluid_vel, nbr_ff, gFff, gIff, W_fluid1, b_fluid1, out1, out1b, 32);
    dense_gemm<3, 32, 4><<<NF/32, 256>>>(fluid_vel, W_d1, b_d1, out1, out1b, 96, 64);

    // layer 2
    dense_gemm<96, 64, 8><<<NF/32, 256>>>(out1, W_d2, b_d2, dense, nullptr, 64, 0);
    cellgemm_kernel<96><<<NF, 128>>>(out1b, nbr_ff, gFff, gIff, (uint32_t*)A);
    gemm_mma<1, 0, 1><<<NF/128, 128, GEMM_SMEM>>>((const __nv_bfloat16*)A, Wb2, b_c2, dense,
                                                  nullptr, out2, out2b, 6144);

    // layer 3
    dense_gemm<64, 64, 8><<<NF/32, 256>>>(out2, W_d3, b_d3, dense, nullptr, 64, 0);
    cellgemm_kernel<64><<<NF, 128>>>(out2b, nbr_ff, gFff, gIff, (uint32_t*)A);
    gemm_mma<1, 1, 1><<<NF/128, 128, GEMM_SMEM>>>((const __nv_bfloat16*)A, Wb3, b_c3, dense,
                                                  out2, out3, nullptr, 4096);

    // layer 4
    pconv4_kernel<<<NF/32, 256>>>(out3, Wp4, (float*)A);
    conv4_kernel<<<NF, 64>>>((const float*)A, nbr_ff, gFff, gIff, b_c4,
                             out3, W_d4, b_d4, (float*)d_out);
}

// round 15
// speedup vs baseline: 1.1357x; 1.0870x over previous
#include <cuda_runtime.h>
#include <cuda_bf16.h>
#include <cstdint>
#include <cstddef>

#define NF   16000
#define KNBR 64
#define RADIUS_F ((float)(0.5*6.0*1.5*0.025))

// ---------------- scratch (device globals; no allocation APIs) ----------------
__device__ float  g_A[(size_t)NF * 64 * 96];   // bf16 A for layers 2/3; fp32 P for layer 4
__device__ float4 g_gF_ff[NF * KNBR];
__device__ int    g_gI_ff[NF * KNBR];
__device__ float4 g_gF_wf[NF * KNBR];
__device__ int    g_gI_wf[NF * KNBR];
__device__ float  g_out1[NF * 96];
__device__ __nv_bfloat16 g_out1b[NF * 96];     // bf16 mirror of out1 (cellgemm gather)
__device__ float  g_out2[NF * 64];
__device__ __nv_bfloat16 g_out2b[NF * 64];     // bf16 mirror of out2
__device__ float  g_out3[NF * 64];
__device__ float  g_dense[NF * 64];
__device__ uint32_t g_Wb2[3072 * 64];          // W_c2 packed bf16x2, [kp][n]
__device__ uint32_t g_Wb3[2048 * 64];          // W_c3 packed bf16x2
__device__ float  g_Wp4[64 * 256];             // W_c4 re-laid [c][cell*4+o], pad o=3 -> 0
__device__ int    g_mask_u8;

// ---------------- helpers ----------------
__device__ __forceinline__ uint32_t smem_u32(const void* p) {
    uint32_t a;
    asm("{ .reg .u64 t; cvta.to.shared.u64 t, %1; cvt.u32.u64 %0, t; }" : "=r"(a) : "l"(p));
    return a;
}
__device__ __forceinline__ void cp16(uint32_t dst, const void* src) {
    asm volatile("cp.async.cg.shared.global [%0], [%1], 16;" :: "r"(dst), "l"(src));
}
#define CP_COMMIT() asm volatile("cp.async.commit_group;" ::: "memory")
__device__ __forceinline__ uint32_t bf16x2(float hi, float lo) {
    uint32_t r;
    asm("cvt.rn.bf16x2.f32 %0, %1, %2;" : "=r"(r) : "f"(hi), "f"(lo));
    return r;
}
__device__ __forceinline__ float fast_sqrt_pos(float m) {   // m > 0
    return m * rsqrtf(m);
}

// ---------------- mask dtype detector ----------------
__global__ void detect_mask_kernel(const unsigned int* __restrict__ m)
{
    __shared__ int s;
    if (threadIdx.x == 0) s = 0;
    __syncthreads();
    int bad = 0;
    for (int i = threadIdx.x; i < 16384; i += blockDim.x)
        if (m[i] > 1u) { bad = 1; break; }
    if (bad) atomicOr(&s, 1);
    __syncthreads();
    if (threadIdx.x == 0) g_mask_u8 = s;
}

// ---------------- geometry (both neighbor sets, fast math) ----------------
static __device__ __forceinline__ float sgnf(float v) {
    return (v > 0.f) ? 1.f : ((v < 0.f) ? -1.f : 0.f);
}
__device__ __forceinline__ void gridmap(float u, int& i0, float& f) {
    float cc = (u * 0.5f + 0.5f) * 3.f;
    cc = fminf(fmaxf(cc, 0.f), 3.f);
    float fi = floorf(cc);
    fi = fminf(fi, 2.f);
    f = cc - fi;
    i0 = (int)fi;
}

__global__ void geom2_kernel(
    const float* __restrict__ fluid_pos, const float* __restrict__ wall_pos,
    const int* __restrict__ nbr_ff, const void* __restrict__ mask_ff,
    float4* __restrict__ gFff, int* __restrict__ gIff,
    const int* __restrict__ nbr_wf, const void* __restrict__ mask_wf,
    float4* __restrict__ gFwf, int* __restrict__ gIwf)
{
    int gidx = blockIdx.x * blockDim.x + threadIdx.x;
    if (gidx >= 2 * NF * KNBR) return;
    int which = gidx >= NF * KNBR;                 // uniform per block
    int idx = which ? gidx - NF * KNBR : gidx;
    const float* pin = which ? wall_pos : fluid_pos;
    const int*   nbr = which ? nbr_wf   : nbr_ff;
    const void*  mask = which ? mask_wf : mask_ff;
    float4* gF = which ? gFwf : gFff;
    int*    gI = which ? gIwf : gIff;

    int mv = g_mask_u8 ? (int)((const unsigned char*)mask)[idx]
                       : ((const int*)mask)[idx];
    if (mv == 0) { gF[idx] = make_float4(0.f, 0.f, 0.f, 0.f); gI[idx] = 0; return; }
    int n = idx >> 6;
    int j = nbr[idx];
    float x = (pin[j*3+0] - fluid_pos[n*3+0]) * (1.f / RADIUS_F);
    float y = (pin[j*3+1] - fluid_pos[n*3+1]) * (1.f / RADIUS_F);
    float z = (pin[j*3+2] - fluid_pos[n*3+2]) * (1.f / RADIUS_F);
    float sq = x*x + y*y + z*z;
    float t1 = 1.f - sq;
    float win = fminf(fmaxf(t1*t1*t1, 0.f), 1.f);

    const float eps = 1e-12f;
    float norm = fast_sqrt_pos(fmaxf(sq, eps));
    float rho  = fast_sqrt_pos(fmaxf(x*x + y*y, eps));
    bool  top  = (1.25f*z*z > x*x + y*y);
    float st_arg = __fdividef(3.f*norm, norm + fabsf(z));
    float s_top = fast_sqrt_pos(st_arg);
    float inv_rho_n = __fdividef(norm, rho);
    float xs = top ? x*s_top : x*inv_rho_n;
    float ys = top ? y*s_top : y*inv_rho_n;
    float zs = top ? sgnf(z)*norm : 1.5f*z;
    if (sq < eps) { xs = 0.f; ys = 0.f; zs = 0.f; }
    float rxy = fast_sqrt_pos(fmaxf(xs*xs + ys*ys, eps));
    bool use_x = fabsf(ys) <= fabsf(xs);
    float ddx = (use_x  && fabsf(xs) > eps) ? xs : 1.f;
    float ddy = (!use_x && fabsf(ys) > eps) ? ys : 1.f;
    const float c4 = 1.27323954473516276487f;  // 4/pi
    float xc = use_x ? sgnf(xs)*rxy : sgnf(ys)*rxy*c4*atanf(__fdividef(xs, ddy));
    float yc = use_x ? sgnf(xs)*rxy*c4*atanf(__fdividef(ys, ddx)) : sgnf(ys)*rxy;
    if (xs*xs + ys*ys < eps) { xc = 0.f; yc = 0.f; }

    int ix, iy, iz; float fx, fy, fz;
    gridmap(xc, ix, fx); gridmap(yc, iy, fy); gridmap(zs, iz, fz);
    gF[idx] = make_float4(fx, fy, fz, win);
    gI[idx] = (ix*4 + iy)*4 + iz;
}

// ---------------- layer-1 cconv (cin=3, cout=32), global-W reads (measured best) ----------
__global__ __launch_bounds__(256) void conv1_kernel(
    const float* __restrict__ feat, const int* __restrict__ nbr,
    const float4* __restrict__ gF, const int* __restrict__ gI,
    const float* __restrict__ W, const float* __restrict__ b,
    float* __restrict__ out1, __nv_bfloat16* __restrict__ out1b, int col0)
{
    __shared__ float A[4][192];
    __shared__ float red[256];
    int t = threadIdx.x;
    int p = t >> 6, tl = t & 63;
    int n = blockIdx.x * 4 + p;
    float* Ap = A[p];
    Ap[tl] = 0.f; Ap[tl + 64] = 0.f; Ap[tl + 128] = 0.f;
    __syncthreads();

    int idx = n * KNBR + tl;
    float4 g = gF[idx];
    if (g.w != 0.f) {
        int j = nbr[idx];
        float f0 = feat[j*3+0]*g.w, f1 = feat[j*3+1]*g.w, f2 = feat[j*3+2]*g.w;
        int base = gI[idx];
        float wx[2] = {1.f - g.x, g.x};
        float wy[2] = {1.f - g.y, g.y};
        float wz[2] = {1.f - g.z, g.z};
        #pragma unroll
        for (int cx = 0; cx < 2; cx++)
        #pragma unroll
        for (int cy = 0; cy < 2; cy++)
        #pragma unroll
        for (int cz = 0; cz < 2; cz++) {
            float wc = wx[cx]*wy[cy]*wz[cz];
            int cell = base + cx*16 + cy*4 + cz;
            atomicAdd(&Ap[cell*3+0], wc*f0);
            atomicAdd(&Ap[cell*3+1], wc*f1);
            atomicAdd(&Ap[cell*3+2], wc*f2);
        }
    }
    __syncthreads();

    int o = tl & 31, h = tl >> 5;
    float acc = 0.f;
    for (int i = h*96; i < h*96 + 96; i++)
        acc += Ap[i] * W[i*32 + o];
    red[t] = acc;
    __syncthreads();
    if (tl < 32) {
        float v = red[p*64 + tl] + red[p*64 + tl + 32] + b[o];
        v = fmaxf(v, 0.f);
        out1 [n*96 + col0 + tl] = v;
        out1b[n*96 + col0 + tl] = __float2bfloat16(v);
    }
}

// ---------------- cellgemm: A[n] = S[n] @ F[n]; F gathered in 4-byte channel pairs -------
#define S_WLDS 36
template<int CIN>
__global__ __launch_bounds__(128) void cellgemm_kernel(
    const __nv_bfloat16* __restrict__ featb, const int* __restrict__ nbr,
    const float4* __restrict__ gF, const int* __restrict__ gI,
    uint32_t* __restrict__ Aout)
{
    constexpr int F_WLDS = CIN + 8;
    constexpr int NT = CIN / 8;
    __shared__ uint32_t sS[64 * S_WLDS];
    __shared__ uint32_t sF[32 * F_WLDS];
    __shared__ float4 sG[KNBR];
    __shared__ int    sJ[KNBR];
    __shared__ int    sB[KNBR];
    int n = blockIdx.x, t = threadIdx.x;
    int w = t >> 5, lane = t & 31;
    int g = lane >> 2, tg = lane & 3;

    if (t < KNBR) { sG[t] = gF[n*KNBR + t]; sB[t] = gI[n*KNBR + t]; sJ[t] = nbr[n*KNBR + t]; }
    for (int i = t; i < 64 * S_WLDS; i += 128) sS[i] = 0;
    __syncthreads();

    if (t < KNBR) {
        float4 gv = sG[t];
        if (gv.w != 0.f) {
            __nv_bfloat16* Sh = (__nv_bfloat16*)sS;
            int base = sB[t];
            float wx0 = (1.f - gv.x) * gv.w, wx1 = gv.x * gv.w;
            float wy0 = 1.f - gv.y, wy1 = gv.y;
            float wz0 = 1.f - gv.z, wz1 = gv.z;
            Sh[(base     ) * (2*S_WLDS) + t] = __float2bfloat16(wx0*wy0*wz0);
            Sh[(base +  1) * (2*S_WLDS) + t] = __float2bfloat16(wx0*wy0*wz1);
            Sh[(base +  4) * (2*S_WLDS) + t] = __float2bfloat16(wx0*wy1*wz0);
            Sh[(base +  5) * (2*S_WLDS) + t] = __float2bfloat16(wx0*wy1*wz1);
            Sh[(base + 16) * (2*S_WLDS) + t] = __float2bfloat16(wx1*wy0*wz0);
            Sh[(base + 17) * (2*S_WLDS) + t] = __float2bfloat16(wx1*wy0*wz1);
            Sh[(base + 20) * (2*S_WLDS) + t] = __float2bfloat16(wx1*wy1*wz0);
            Sh[(base + 21) * (2*S_WLDS) + t] = __float2bfloat16(wx1*wy1*wz1);
        }
    }

    // F gather: thread handles a channel PAIR (4B aligned) from 2 neighbors,
    // splits into interleaved layout with byte-perm. Half the LDG count.
    {
        const uint32_t* fb = (const uint32_t*)featb;
        for (int i = t; i < 16 * CIN; i += 128) {        // (kp, c2) pairs
            int kp = i / (CIN/2), c2 = i - kp * (CIN/2);
            uint32_t u0 = fb[(size_t)sJ[2*kp    ] * (CIN/2) + c2];   // j0: ch (2c2, 2c2+1)
            uint32_t u1 = fb[(size_t)sJ[2*kp + 1] * (CIN/2) + c2];   // j1: ch (2c2, 2c2+1)
            sF[kp * F_WLDS + 2*c2    ] = __byte_perm(u0, u1, 0x5410);  // (j1.lo, j0.lo)
            sF[kp * F_WLDS + 2*c2 + 1] = __byte_perm(u0, u1, 0x7632);  // (j1.hi, j0.hi)
        }
    }
    __syncthreads();

    float acc[NT][4];
    #pragma unroll
    for (int nt = 0; nt < NT; nt++)
        #pragma unroll
        for (int q = 0; q < 4; q++) acc[nt][q] = 0.f;

    #pragma unroll
    for (int q = 0; q < 4; q++) {
        int r = w * 16 + g;
        uint32_t a0 = sS[(r    ) * S_WLDS + 8*q + tg    ];
        uint32_t a1 = sS[(r + 8) * S_WLDS + 8*q + tg    ];
        uint32_t a2 = sS[(r    ) * S_WLDS + 8*q + tg + 4];
        uint32_t a3 = sS[(r + 8) * S_WLDS + 8*q + tg + 4];
        #pragma unroll
        for (int nt = 0; nt < NT; nt++) {
            uint32_t b0 = sF[(8*q + tg    ) * F_WLDS + nt * 8 + g];
            uint32_t b1 = sF[(8*q + tg + 4) * F_WLDS + nt * 8 + g];
            asm volatile(
                "mma.sync.aligned.m16n8k16.row.col.f32.bf16.bf16.f32 "
                "{%0,%1,%2,%3},{%4,%5,%6,%7},{%8,%9},{%0,%1,%2,%3};"
                : "+f"(acc[nt][0]), "+f"(acc[nt][1]), "+f"(acc[nt][2]), "+f"(acc[nt][3])
                : "r"(a0), "r"(a1), "r"(a2), "r"(a3), "r"(b0), "r"(b1));
        }
    }

    uint32_t* out = Aout + (size_t)n * (32 * CIN);
    #pragma unroll
    for (int nt = 0; nt < NT; nt++) {
        #pragma unroll
        for (int h = 0; h < 2; h++) {
            int cell = w * 16 + g + h * 8;
            out[cell * (CIN/2) + nt * 4 + tg] = bf16x2(acc[nt][h*2+1], acc[nt][h*2+0]);
        }
    }
}

// ---------------- merged weight prep ----------------
#define N_WB2 (3072 * 64)
#define N_WB3 (2048 * 64)
#define N_WP4 (64 * 256)
__global__ void pack_all_kernel(
    const float* __restrict__ W2, const float* __restrict__ W3, const float* __restrict__ W4,
    uint32_t* __restrict__ Wb2, uint32_t* __restrict__ Wb3, float* __restrict__ Wp4)
{
    int idx = blockIdx.x * blockDim.x + threadIdx.x;
    if (idx < N_WB2) {
        int kp = idx >> 6, n = idx & 63;
        Wb2[idx] = bf16x2(W2[(size_t)(2*kp+1)*64 + n], W2[(size_t)(2*kp)*64 + n]);
    } else if (idx < N_WB2 + N_WB3) {
        int j = idx - N_WB2;
        int kp = j >> 6, n = j & 63;
        Wb3[j] = bf16x2(W3[(size_t)(2*kp+1)*64 + n], W3[(size_t)(2*kp)*64 + n]);
    } else if (idx < N_WB2 + N_WB3 + N_WP4) {
        int j = idx - N_WB2 - N_WB3;
        int c = j >> 8, col = j & 255;
        int cell = col >> 2, o = col & 3;
        Wp4[j] = (o < 3) ? W4[((size_t)cell * 64 + c) * 3 + o] : 0.f;
    }
}

// ---------------- pconv4 ----------------
__global__ __launch_bounds__(256) void pconv4_kernel(
    const float* __restrict__ X, const float* __restrict__ Wp, float* __restrict__ P)
{
    __shared__ float4 Xs[32][16];
    int t = threadIdx.x;
    int n0 = blockIdx.x * 32;
    for (int i = t; i < 512; i += 256) {
        int r = i >> 4, c4 = i & 15;
        Xs[r][c4] = *(const float4*)(X + (size_t)(n0 + r) * 64 + c4 * 4);
    }
    __syncthreads();

    float acc[32];
    #pragma unroll
    for (int r = 0; r < 32; r++) acc[r] = 0.f;
    #pragma unroll
    for (int c4 = 0; c4 < 16; c4++) {
        float w0 = Wp[(c4*4 + 0) * 256 + t];
        float w1 = Wp[(c4*4 + 1) * 256 + t];
        float w2 = Wp[(c4*4 + 2) * 256 + t];
        float w3 = Wp[(c4*4 + 3) * 256 + t];
        #pragma unroll
        for (int r = 0; r < 32; r++) {
            float4 xv = Xs[r][c4];
            acc[r] += xv.x*w0 + xv.y*w1 + xv.z*w2 + xv.w*w3;
        }
    }
    #pragma unroll
    for (int r = 0; r < 32; r++)
        P[(size_t)(n0 + r) * 256 + t] = acc[r];
}

// ---------------- conv4 gather + fused dense shortcut ----------------
__global__ __launch_bounds__(64) void conv4_kernel(
    const float* __restrict__ P, const int* __restrict__ nbr,
    const float4* __restrict__ gF, const int* __restrict__ gI,
    const float* __restrict__ bc4, const float* __restrict__ out3,
    const float* __restrict__ Wd4, const float* __restrict__ bd4,
    float* __restrict__ out)
{
    __shared__ float red[2][3];
    int n = blockIdx.x, t = threadIdx.x;
    float a0 = 0.f, a1 = 0.f, a2 = 0.f;
    {
        float x = out3[(size_t)n * 64 + t];
        a0 += x * Wd4[t*3 + 0];
        a1 += x * Wd4[t*3 + 1];
        a2 += x * Wd4[t*3 + 2];
    }
    float4 g = gF[n*KNBR + t];
    if (g.w != 0.f) {
        int j = nbr[n*KNBR + t];
        const float4* Pj = (const float4*)(P + (size_t)j * 256);
        int base = gI[n*KNBR + t];
        float wx0 = (1.f - g.x) * g.w, wx1 = g.x * g.w;
        float wy0 = 1.f - g.y, wy1 = g.y;
        float wz0 = 1.f - g.z, wz1 = g.z;
        float wq[8] = {wx0*wy0*wz0, wx0*wy0*wz1, wx0*wy1*wz0, wx0*wy1*wz1,
                       wx1*wy0*wz0, wx1*wy0*wz1, wx1*wy1*wz0, wx1*wy1*wz1};
        const int off[8] = {0, 1, 4, 5, 16, 17, 20, 21};
        #pragma unroll
        for (int q = 0; q < 8; q++) {
            float4 p = Pj[base + off[q]];
            a0 += wq[q] * p.x; a1 += wq[q] * p.y; a2 += wq[q] * p.z;
        }
    }
    #pragma unroll
    for (int s = 16; s > 0; s >>= 1) {
        a0 += __shfl_down_sync(0xffffffff, a0, s);
        a1 += __shfl_down_sync(0xffffffff, a1, s);
        a2 += __shfl_down_sync(0xffffffff, a2, s);
    }
    if ((t & 31) == 0) { red[t>>5][0] = a0; red[t>>5][1] = a1; red[t>>5][2] = a2; }
    __syncthreads();
    if (t < 3) out[n*3 + t] = red[0][t] + red[1][t] + bc4[t] + bd4[t];
}

// ---------------- bf16 tensor GEMM: M-tile 128 (measured best) ----------------
#define STAGES 4
#define A_WLDS 20
#define B_WLDS 72
#define A_WSTAGE (128*A_WLDS)
#define B_WSTAGE (16*B_WLDS)
#define GEMM_SMEM (STAGES*(A_WSTAGE + B_WSTAGE)*4)

template<int HAS_ADD, int HAS_RES, int RELU>
__global__ __launch_bounds__(128) void gemm_mma(
    const __nv_bfloat16* __restrict__ Ag, const uint32_t* __restrict__ Wb,
    const float* __restrict__ bias, const float* __restrict__ addv,
    const float* __restrict__ resv, float* __restrict__ out,
    __nv_bfloat16* __restrict__ outb, int K)
{
    extern __shared__ uint32_t sm[];
    uint32_t* sA = sm;
    uint32_t* sB = sm + STAGES * A_WSTAGE;
    int tid = threadIdx.x, w = tid >> 5, lane = tid & 31;
    int g = lane >> 2, tg = lane & 3;
    int m0 = blockIdx.x * 128;
    int NIT = K >> 5;
    uint32_t sAu = smem_u32(sA), sBu = smem_u32(sB);

    auto load_stage = [&](int s, int c) {
        uint32_t ab = sAu + (uint32_t)s * A_WSTAGE * 4;
        const __nv_bfloat16* as = Ag + (size_t)m0 * K + c * 32;
        #pragma unroll
        for (int r = 0; r < 4; r++) {
            int idx = r * 128 + tid;
            int row = idx >> 2, seg = idx & 3;
            cp16(ab + (row * A_WLDS + seg * 4) * 4, as + (size_t)row * K + seg * 8);
        }
        uint32_t bb = sBu + (uint32_t)s * B_WSTAGE * 4;
        const uint32_t* bs = Wb + (size_t)c * 16 * 64;
        #pragma unroll
        for (int r = 0; r < 2; r++) {
            int idx = r * 128 + tid;
            int kp = idx >> 4, seg = idx & 15;
            cp16(bb + (kp * B_WLDS + seg * 4) * 4, bs + kp * 64 + seg * 4);
        }
    };

    float acc[2][8][4];
    #pragma unroll
    for (int mt = 0; mt < 2; mt++)
        #pragma unroll
        for (int nt = 0; nt < 8; nt++)
            #pragma unroll
            for (int q = 0; q < 4; q++) acc[mt][nt][q] = 0.f;

    #pragma unroll
    for (int s = 0; s < STAGES; s++) { load_stage(s, s); CP_COMMIT(); }

    for (int i = 0; i < NIT; i++) {
        asm volatile("cp.async.wait_group %0;" :: "n"(STAGES - 1));
        __syncthreads();
        const uint32_t* cA = sA + (i % STAGES) * A_WSTAGE;
        const uint32_t* cB = sB + (i % STAGES) * B_WSTAGE;
        #pragma unroll
        for (int q = 0; q < 2; q++) {
            uint32_t a[2][4], b[8][2];
            #pragma unroll
            for (int mt = 0; mt < 2; mt++) {
                int r = w * 32 + mt * 16 + g;
                a[mt][0] = cA[(r    ) * A_WLDS + 8*q + tg    ];
                a[mt][1] = cA[(r + 8) * A_WLDS + 8*q + tg    ];
                a[mt][2] = cA[(r    ) * A_WLDS + 8*q + tg + 4];
                a[mt][3] = cA[(r + 8) * A_WLDS + 8*q + tg + 4];
            }
            #pragma unroll
            for (int nt = 0; nt < 8; nt++) {
                b[nt][0] = cB[(8*q + tg    ) * B_WLDS + nt * 8 + g];
                b[nt][1] = cB[(8*q + tg + 4) * B_WLDS + nt * 8 + g];
            }
            #pragma unroll
            for (int mt = 0; mt < 2; mt++)
                #pragma unroll
                for (int nt = 0; nt < 8; nt++)
                    asm volatile(
                        "mma.sync.aligned.m16n8k16.row.col.f32.bf16.bf16.f32 "
                        "{%0,%1,%2,%3},{%4,%5,%6,%7},{%8,%9},{%0,%1,%2,%3};"
                        : "+f"(acc[mt][nt][0]), "+f"(acc[mt][nt][1]),
                          "+f"(acc[mt][nt][2]), "+f"(acc[mt][nt][3])
                        : "r"(a[mt][0]), "r"(a[mt][1]), "r"(a[mt][2]), "r"(a[mt][3]),
                          "r"(b[nt][0]), "r"(b[nt][1]));
        }
        __syncthreads();
        if (i + STAGES < NIT) load_stage(i % STAGES, i + STAGES);
        CP_COMMIT();
    }

    #pragma unroll
    for (int mt = 0; mt < 2; mt++) {
        #pragma unroll
        for (int nt = 0; nt < 8; nt++) {
            #pragma unroll
            for (int h = 0; h < 2; h++) {
                int m = m0 + w * 32 + mt * 16 + g + h * 8;
                int n0 = nt * 8 + 2 * tg;
                float lo = acc[mt][nt][h*2+0], hi = acc[mt][nt][h*2+1];
                float2 bb = *(const float2*)&bias[n0];
                lo += bb.x; hi += bb.y;
                if (HAS_ADD) {
                    float2 v = *(const float2*)&addv[(size_t)m*64 + n0];
                    lo += v.x; hi += v.y;
                }
                if (HAS_RES) {
                    float2 v = *(const float2*)&resv[(size_t)m*64 + n0];
                    lo += v.x; hi += v.y;
                }
                if (RELU) { lo = fmaxf(lo, 0.f); hi = fmaxf(hi, 0.f); }
                *(float2*)&out[(size_t)m*64 + n0] = make_float2(lo, hi);
                if (outb)
                    *(uint32_t*)&outb[(size_t)m*64 + n0] = bf16x2(hi, lo);
            }
        }
    }
}

// ---------------- dense GEMM ----------------
template<int CIN, int COUT, int RPT>
__global__ __launch_bounds__(COUT * (32 / RPT)) void dense_gemm(
    const float* __restrict__ X, const float* __restrict__ W,
    const float* __restrict__ b, float* __restrict__ Y,
    __nv_bfloat16* __restrict__ Yb, int ldY, int col0)
{
    constexpr int BD = COUT * (32 / RPT);
    __shared__ float Xs[32 * CIN];
    int t = threadIdx.x;
    int n0 = blockIdx.x * 32;
    for (int i = t; i < 32 * CIN; i += BD)
        Xs[i] = X[(size_t)n0 * CIN + i];
    __syncthreads();

    int o = t % COUT, rg = t / COUT;
    float acc[RPT];
    float bo = b[o];
    #pragma unroll
    for (int r = 0; r < RPT; r++) acc[r] = bo;
    #pragma unroll 4
    for (int c = 0; c < CIN; c++) {
        float wv = W[c * COUT + o];
        #pragma unroll
        for (int r = 0; r < RPT; r++)
            acc[r] += Xs[(rg * RPT + r) * CIN + c] * wv;
    }
    #pragma unroll
    for (int r = 0; r < RPT; r++) {
        size_t off = (size_t)(n0 + rg * RPT + r) * ldY + col0 + o;
        Y[off] = acc[r];
        if (Yb) Yb[off] = __float2bfloat16(acc[r]);
    }
}

// ---------------- launch ----------------
extern "C" void kernel_launch(void* const* d_in, const int* in_sizes, int n_in,
                              void* d_out, int out_size)
{
    const float* fluid_pos = (const float*)d_in[0];
    const float* wall_pos  = (const float*)d_in[1];
    const float* fluid_vel = (const float*)d_in[2];
    const float* wall_nv   = (const float*)d_in[3];
    const int*   nbr_wf    = (const int*)d_in[4];
    const void*  mask_wf   = d_in[5];
    const int*   nbr_ff    = (const int*)d_in[6];
    const void*  mask_ff   = d_in[7];
    const float* W_wall1 = (const float*)d_in[8];
    const float* b_wall1 = (const float*)d_in[9];
    const float* W_fluid1 = (const float*)d_in[10];
    const float* b_fluid1 = (const float*)d_in[11];
    const float* W_d1 = (const float*)d_in[12];
    const float* b_d1 = (const float*)d_in[13];
    const float* W_c2 = (const float*)d_in[14];
    const float* b_c2 = (const float*)d_in[15];
    const float* W_d2 = (const float*)d_in[16];
    const float* b_d2 = (const float*)d_in[17];
    const float* W_c3 = (const float*)d_in[18];
    const float* b_c3 = (const float*)d_in[19];
    const float* W_d3 = (const float*)d_in[20];
    const float* b_d3 = (const float*)d_in[21];
    const float* W_c4 = (const float*)d_in[22];
    const float* b_c4 = (const float*)d_in[23];
    const float* W_d4 = (const float*)d_in[24];
    const float* b_d4 = (const float*)d_in[25];

    void *pA, *pgFff, *pgIff, *pgFwf, *pgIwf, *pout1, *pout1b, *pout2, *pout2b,
         *pout3, *pdense, *pWb2, *pWb3, *pWp4;
    cudaGetSymbolAddress(&pA, g_A);
    cudaGetSymbolAddress(&pgFff, g_gF_ff);
    cudaGetSymbolAddress(&pgIff, g_gI_ff);
    cudaGetSymbolAddress(&pgFwf, g_gF_wf);
    cudaGetSymbolAddress(&pgIwf, g_gI_wf);
    cudaGetSymbolAddress(&pout1, g_out1);
    cudaGetSymbolAddress(&pout1b, g_out1b);
    cudaGetSymbolAddress(&pout2, g_out2);
    cudaGetSymbolAddress(&pout2b, g_out2b);
    cudaGetSymbolAddress(&pout3, g_out3);
    cudaGetSymbolAddress(&pdense, g_dense);
    cudaGetSymbolAddress(&pWb2, g_Wb2);
    cudaGetSymbolAddress(&pWb3, g_Wb3);
    cudaGetSymbolAddress(&pWp4, g_Wp4);
    void*   A     = pA;
    float4* gFff  = (float4*)pgFff;
    int*    gIff  = (int*)pgIff;
    float4* gFwf  = (float4*)pgFwf;
    int*    gIwf  = (int*)pgIwf;
    float*  out1  = (float*)pout1;
    __nv_bfloat16* out1b = (__nv_bfloat16*)pout1b;
    float*  out2  = (float*)pout2;
    __nv_bfloat16* out2b = (__nv_bfloat16*)pout2b;
    float*  out3  = (float*)pout3;
    float*  dense = (float*)pdense;
    uint32_t* Wb2 = (uint32_t*)pWb2;
    uint32_t* Wb3 = (uint32_t*)pWb3;
    float*  Wp4   = (float*)pWp4;

    cudaFuncSetAttribute(gemm_mma<1,0,1>, cudaFuncAttributeMaxDynamicSharedMemorySize, GEMM_SMEM);
    cudaFuncSetAttribute(gemm_mma<1,1,1>, cudaFuncAttributeMaxDynamicSharedMemorySize, GEMM_SMEM);

    const int tot = NF * KNBR;
    detect_mask_kernel<<<1, 1024>>>((const unsigned int*)mask_wf);
    geom2_kernel<<<(2*tot + 255)/256, 256>>>(fluid_pos, wall_pos,
                                             nbr_ff, mask_ff, gFff, gIff,
                                             nbr_wf, mask_wf, gFwf, gIwf);
    pack_all_kernel<<<(N_WB2 + N_WB3 + N_WP4 + 255)/256, 256>>>(W_c2, W_c3, W_c4, Wb2, Wb3, Wp4);

    // layer 1
    conv1_kernel<<<NF/4, 256>>>(wall_nv,   nbr_wf, gFwf, gIwf, W_wall1,  b_wall1,  out1, out1b, 0);
    conv1_kernel<<<NF/4, 256>>>(fluid_vel, nbr_ff, gFff, gIff, W_fluid1, b_fluid1, out1, out1b, 32);
    dense_gemm<3, 32, 4><<<NF/32, 256>>>(fluid_vel, W_d1, b_d1, out1, out1b, 96, 64);

    // layer 2
    dense_gemm<96, 64, 8><<<NF/32, 256>>>(out1, W_d2, b_d2, dense, nullptr, 64, 0);
    cellgemm_kernel<96><<<NF, 128>>>(out1b, nbr_ff, gFff, gIff, (uint32_t*)A);
    gemm_mma<1, 0, 1><<<NF/128, 128, GEMM_SMEM>>>((const __nv_bfloat16*)A, Wb2, b_c2, dense,
                                                  nullptr, out2, out2b, 6144);

    // layer 3
    dense_gemm<64, 64, 8><<<NF/32, 256>>>(out2, W_d3, b_d3, dense, nullptr, 64, 0);
    cellgemm_kernel<64><<<NF, 128>>>(out2b, nbr_ff, gFff, gIff, (uint32_t*)A);
    gemm_mma<1, 1, 1><<<NF/128, 128, GEMM_SMEM>>>((const __nv_bfloat16*)A, Wb3, b_c3, dense,
                                                  out2, out3, nullptr, 4096);

    // layer 4
    pconv4_kernel<<<NF/32, 256>>>(out3, Wp4, (float*)A);
    conv4_kernel<<<NF, 64>>>((const float*)A, nbr_ff, gFff, gIff, b_c4,
                             out3, W_d4, b_d4, (float*)d_out);
}

// round 16
// speedup vs baseline: 1.1457x; 1.0088x over previous
#include <cuda_runtime.h>
#include <cuda_bf16.h>
#include <cstdint>
#include <cstddef>

#define NF   16000
#define KNBR 64
#define RADIUS_F ((float)(0.5*6.0*1.5*0.025))

// ---------------- scratch (device globals; no allocation APIs) ----------------
__device__ float  g_A[(size_t)NF * 64 * 96];   // bf16 A for layers 2/3; fp32 P for layer 4
__device__ float4 g_gF_ff[NF * KNBR];
__device__ int    g_gI_ff[NF * KNBR];
__device__ float4 g_gF_wf[NF * KNBR];
__device__ int    g_gI_wf[NF * KNBR];
__device__ float  g_out1[NF * 96];
__device__ __nv_bfloat16 g_out1b[NF * 96];
__device__ float  g_out2[NF * 64];
__device__ __nv_bfloat16 g_out2b[NF * 64];
__device__ float  g_out3[NF * 64];
__device__ float  g_dense[NF * 64];
__device__ uint32_t g_Wb2[3072 * 64];
__device__ uint32_t g_Wb3[2048 * 64];
__device__ float  g_Wp4[64 * 256];
__device__ int    g_mask_u8;

// ---------------- helpers ----------------
__device__ __forceinline__ uint32_t smem_u32(const void* p) {
    uint32_t a;
    asm("{ .reg .u64 t; cvta.to.shared.u64 t, %1; cvt.u32.u64 %0, t; }" : "=r"(a) : "l"(p));
    return a;
}
__device__ __forceinline__ void cp16(uint32_t dst, const void* src) {
    asm volatile("cp.async.cg.shared.global [%0], [%1], 16;" :: "r"(dst), "l"(src));
}
#define CP_COMMIT() asm volatile("cp.async.commit_group;" ::: "memory")
__device__ __forceinline__ uint32_t bf16x2(float hi, float lo) {
    uint32_t r;
    asm("cvt.rn.bf16x2.f32 %0, %1, %2;" : "=r"(r) : "f"(hi), "f"(lo));
    return r;
}
__device__ __forceinline__ float fast_sqrt_pos(float m) {
    return m * rsqrtf(m);
}

// ---------------- mask dtype detector ----------------
__global__ void detect_mask_kernel(const unsigned int* __restrict__ m)
{
    __shared__ int s;
    if (threadIdx.x == 0) s = 0;
    __syncthreads();
    int bad = 0;
    for (int i = threadIdx.x; i < 16384; i += blockDim.x)
        if (m[i] > 1u) { bad = 1; break; }
    if (bad) atomicOr(&s, 1);
    __syncthreads();
    if (threadIdx.x == 0) g_mask_u8 = s;
}

// ---------------- geometry (both neighbor sets, fast math) ----------------
static __device__ __forceinline__ float sgnf(float v) {
    return (v > 0.f) ? 1.f : ((v < 0.f) ? -1.f : 0.f);
}
__device__ __forceinline__ void gridmap(float u, int& i0, float& f) {
    float cc = (u * 0.5f + 0.5f) * 3.f;
    cc = fminf(fmaxf(cc, 0.f), 3.f);
    float fi = floorf(cc);
    fi = fminf(fi, 2.f);
    f = cc - fi;
    i0 = (int)fi;
}

__global__ void geom2_kernel(
    const float* __restrict__ fluid_pos, const float* __restrict__ wall_pos,
    const int* __restrict__ nbr_ff, const void* __restrict__ mask_ff,
    float4* __restrict__ gFff, int* __restrict__ gIff,
    const int* __restrict__ nbr_wf, const void* __restrict__ mask_wf,
    float4* __restrict__ gFwf, int* __restrict__ gIwf)
{
    int gidx = blockIdx.x * blockDim.x + threadIdx.x;
    if (gidx >= 2 * NF * KNBR) return;
    int which = gidx >= NF * KNBR;
    int idx = which ? gidx - NF * KNBR : gidx;
    const float* pin = which ? wall_pos : fluid_pos;
    const int*   nbr = which ? nbr_wf   : nbr_ff;
    const void*  mask = which ? mask_wf : mask_ff;
    float4* gF = which ? gFwf : gFff;
    int*    gI = which ? gIwf : gIff;

    int mv = g_mask_u8 ? (int)((const unsigned char*)mask)[idx]
                       : ((const int*)mask)[idx];
    if (mv == 0) { gF[idx] = make_float4(0.f, 0.f, 0.f, 0.f); gI[idx] = 0; return; }
    int n = idx >> 6;
    int j = nbr[idx];
    float x = (pin[j*3+0] - fluid_pos[n*3+0]) * (1.f / RADIUS_F);
    float y = (pin[j*3+1] - fluid_pos[n*3+1]) * (1.f / RADIUS_F);
    float z = (pin[j*3+2] - fluid_pos[n*3+2]) * (1.f / RADIUS_F);
    float sq = x*x + y*y + z*z;
    float t1 = 1.f - sq;
    float win = fminf(fmaxf(t1*t1*t1, 0.f), 1.f);

    const float eps = 1e-12f;
    float norm = fast_sqrt_pos(fmaxf(sq, eps));
    float rho  = fast_sqrt_pos(fmaxf(x*x + y*y, eps));
    bool  top  = (1.25f*z*z > x*x + y*y);
    float st_arg = __fdividef(3.f*norm, norm + fabsf(z));
    float s_top = fast_sqrt_pos(st_arg);
    float inv_rho_n = __fdividef(norm, rho);
    float xs = top ? x*s_top : x*inv_rho_n;
    float ys = top ? y*s_top : y*inv_rho_n;
    float zs = top ? sgnf(z)*norm : 1.5f*z;
    if (sq < eps) { xs = 0.f; ys = 0.f; zs = 0.f; }
    float rxy = fast_sqrt_pos(fmaxf(xs*xs + ys*ys, eps));
    bool use_x = fabsf(ys) <= fabsf(xs);
    float ddx = (use_x  && fabsf(xs) > eps) ? xs : 1.f;
    float ddy = (!use_x && fabsf(ys) > eps) ? ys : 1.f;
    const float c4 = 1.27323954473516276487f;  // 4/pi
    float xc = use_x ? sgnf(xs)*rxy : sgnf(ys)*rxy*c4*atanf(__fdividef(xs, ddy));
    float yc = use_x ? sgnf(xs)*rxy*c4*atanf(__fdividef(ys, ddx)) : sgnf(ys)*rxy;
    if (xs*xs + ys*ys < eps) { xc = 0.f; yc = 0.f; }

    int ix, iy, iz; float fx, fy, fz;
    gridmap(xc, ix, fx); gridmap(yc, iy, fy); gridmap(zs, iz, fz);
    gF[idx] = make_float4(fx, fy, fz, win);
    gI[idx] = (ix*4 + iy)*4 + iz;
}

// ---------------- layer-1 cconv (cin=3, cout=32), global-W reads (measured best) ----------
__global__ __launch_bounds__(256) void conv1_kernel(
    const float* __restrict__ feat, const int* __restrict__ nbr,
    const float4* __restrict__ gF, const int* __restrict__ gI,
    const float* __restrict__ W, const float* __restrict__ b,
    float* __restrict__ out1, __nv_bfloat16* __restrict__ out1b, int col0)
{
    __shared__ float A[4][192];
    __shared__ float red[256];
    int t = threadIdx.x;
    int p = t >> 6, tl = t & 63;
    int n = blockIdx.x * 4 + p;
    float* Ap = A[p];
    Ap[tl] = 0.f; Ap[tl + 64] = 0.f; Ap[tl + 128] = 0.f;
    __syncthreads();

    int idx = n * KNBR + tl;
    float4 g = gF[idx];
    if (g.w != 0.f) {
        int j = nbr[idx];
        float f0 = feat[j*3+0]*g.w, f1 = feat[j*3+1]*g.w, f2 = feat[j*3+2]*g.w;
        int base = gI[idx];
        float wx[2] = {1.f - g.x, g.x};
        float wy[2] = {1.f - g.y, g.y};
        float wz[2] = {1.f - g.z, g.z};
        #pragma unroll
        for (int cx = 0; cx < 2; cx++)
        #pragma unroll
        for (int cy = 0; cy < 2; cy++)
        #pragma unroll
        for (int cz = 0; cz < 2; cz++) {
            float wc = wx[cx]*wy[cy]*wz[cz];
            int cell = base + cx*16 + cy*4 + cz;
            atomicAdd(&Ap[cell*3+0], wc*f0);
            atomicAdd(&Ap[cell*3+1], wc*f1);
            atomicAdd(&Ap[cell*3+2], wc*f2);
        }
    }
    __syncthreads();

    int o = tl & 31, h = tl >> 5;
    float acc = 0.f;
    for (int i = h*96; i < h*96 + 96; i++)
        acc += Ap[i] * W[i*32 + o];
    red[t] = acc;
    __syncthreads();
    if (tl < 32) {
        float v = red[p*64 + tl] + red[p*64 + tl + 32] + b[o];
        v = fmaxf(v, 0.f);
        out1 [n*96 + col0 + tl] = v;
        out1b[n*96 + col0 + tl] = __float2bfloat16(v);
    }
}

// ---------------- cellgemm: A[n] = S[n] @ F[n]; F gathered in 4-byte channel pairs -------
#define S_WLDS 36
template<int CIN>
__global__ __launch_bounds__(128) void cellgemm_kernel(
    const __nv_bfloat16* __restrict__ featb, const int* __restrict__ nbr,
    const float4* __restrict__ gF, const int* __restrict__ gI,
    uint32_t* __restrict__ Aout)
{
    constexpr int F_WLDS = CIN + 8;
    constexpr int NT = CIN / 8;
    __shared__ uint32_t sS[64 * S_WLDS];
    __shared__ uint32_t sF[32 * F_WLDS];
    __shared__ float4 sG[KNBR];
    __shared__ int    sJ[KNBR];
    __shared__ int    sB[KNBR];
    int n = blockIdx.x, t = threadIdx.x;
    int w = t >> 5, lane = t & 31;
    int g = lane >> 2, tg = lane & 3;

    if (t < KNBR) { sG[t] = gF[n*KNBR + t]; sB[t] = gI[n*KNBR + t]; sJ[t] = nbr[n*KNBR + t]; }
    for (int i = t; i < 64 * S_WLDS; i += 128) sS[i] = 0;
    __syncthreads();

    if (t < KNBR) {
        float4 gv = sG[t];
        if (gv.w != 0.f) {
            __nv_bfloat16* Sh = (__nv_bfloat16*)sS;
            int base = sB[t];
            float wx0 = (1.f - gv.x) * gv.w, wx1 = gv.x * gv.w;
            float wy0 = 1.f - gv.y, wy1 = gv.y;
            float wz0 = 1.f - gv.z, wz1 = gv.z;
            Sh[(base     ) * (2*S_WLDS) + t] = __float2bfloat16(wx0*wy0*wz0);
            Sh[(base +  1) * (2*S_WLDS) + t] = __float2bfloat16(wx0*wy0*wz1);
            Sh[(base +  4) * (2*S_WLDS) + t] = __float2bfloat16(wx0*wy1*wz0);
            Sh[(base +  5) * (2*S_WLDS) + t] = __float2bfloat16(wx0*wy1*wz1);
            Sh[(base + 16) * (2*S_WLDS) + t] = __float2bfloat16(wx1*wy0*wz0);
            Sh[(base + 17) * (2*S_WLDS) + t] = __float2bfloat16(wx1*wy0*wz1);
            Sh[(base + 20) * (2*S_WLDS) + t] = __float2bfloat16(wx1*wy1*wz0);
            Sh[(base + 21) * (2*S_WLDS) + t] = __float2bfloat16(wx1*wy1*wz1);
        }
    }

    {
        const uint32_t* fb = (const uint32_t*)featb;
        for (int i = t; i < 16 * CIN; i += 128) {
            int kp = i / (CIN/2), c2 = i - kp * (CIN/2);
            uint32_t u0 = fb[(size_t)sJ[2*kp    ] * (CIN/2) + c2];
            uint32_t u1 = fb[(size_t)sJ[2*kp + 1] * (CIN/2) + c2];
            sF[kp * F_WLDS + 2*c2    ] = __byte_perm(u0, u1, 0x5410);
            sF[kp * F_WLDS + 2*c2 + 1] = __byte_perm(u0, u1, 0x7632);
        }
    }
    __syncthreads();

    float acc[NT][4];
    #pragma unroll
    for (int nt = 0; nt < NT; nt++)
        #pragma unroll
        for (int q = 0; q < 4; q++) acc[nt][q] = 0.f;

    #pragma unroll
    for (int q = 0; q < 4; q++) {
        int r = w * 16 + g;
        uint32_t a0 = sS[(r    ) * S_WLDS + 8*q + tg    ];
        uint32_t a1 = sS[(r + 8) * S_WLDS + 8*q + tg    ];
        uint32_t a2 = sS[(r    ) * S_WLDS + 8*q + tg + 4];
        uint32_t a3 = sS[(r + 8) * S_WLDS + 8*q + tg + 4];
        #pragma unroll
        for (int nt = 0; nt < NT; nt++) {
            uint32_t b0 = sF[(8*q + tg    ) * F_WLDS + nt * 8 + g];
            uint32_t b1 = sF[(8*q + tg + 4) * F_WLDS + nt * 8 + g];
            asm volatile(
                "mma.sync.aligned.m16n8k16.row.col.f32.bf16.bf16.f32 "
                "{%0,%1,%2,%3},{%4,%5,%6,%7},{%8,%9},{%0,%1,%2,%3};"
                : "+f"(acc[nt][0]), "+f"(acc[nt][1]), "+f"(acc[nt][2]), "+f"(acc[nt][3])
                : "r"(a0), "r"(a1), "r"(a2), "r"(a3), "r"(b0), "r"(b1));
        }
    }

    uint32_t* out = Aout + (size_t)n * (32 * CIN);
    #pragma unroll
    for (int nt = 0; nt < NT; nt++) {
        #pragma unroll
        for (int h = 0; h < 2; h++) {
            int cell = w * 16 + g + h * 8;
            out[cell * (CIN/2) + nt * 4 + tg] = bf16x2(acc[nt][h*2+1], acc[nt][h*2+0]);
        }
    }
}

// ---------------- merged weight prep ----------------
#define N_WB2 (3072 * 64)
#define N_WB3 (2048 * 64)
#define N_WP4 (64 * 256)
__global__ void pack_all_kernel(
    const float* __restrict__ W2, const float* __restrict__ W3, const float* __restrict__ W4,
    uint32_t* __restrict__ Wb2, uint32_t* __restrict__ Wb3, float* __restrict__ Wp4)
{
    int idx = blockIdx.x * blockDim.x + threadIdx.x;
    if (idx < N_WB2) {
        int kp = idx >> 6, n = idx & 63;
        Wb2[idx] = bf16x2(W2[(size_t)(2*kp+1)*64 + n], W2[(size_t)(2*kp)*64 + n]);
    } else if (idx < N_WB2 + N_WB3) {
        int j = idx - N_WB2;
        int kp = j >> 6, n = j & 63;
        Wb3[j] = bf16x2(W3[(size_t)(2*kp+1)*64 + n], W3[(size_t)(2*kp)*64 + n]);
    } else if (idx < N_WB2 + N_WB3 + N_WP4) {
        int j = idx - N_WB2 - N_WB3;
        int c = j >> 8, col = j & 255;
        int cell = col >> 2, o = col & 3;
        Wp4[j] = (o < 3) ? W4[((size_t)cell * 64 + c) * 3 + o] : 0.f;
    }
}

// ---------------- pconv4 ----------------
__global__ __launch_bounds__(256) void pconv4_kernel(
    const float* __restrict__ X, const float* __restrict__ Wp, float* __restrict__ P)
{
    __shared__ float4 Xs[32][16];
    int t = threadIdx.x;
    int n0 = blockIdx.x * 32;
    for (int i = t; i < 512; i += 256) {
        int r = i >> 4, c4 = i & 15;
        Xs[r][c4] = *(const float4*)(X + (size_t)(n0 + r) * 64 + c4 * 4);
    }
    __syncthreads();

    float acc[32];
    #pragma unroll
    for (int r = 0; r < 32; r++) acc[r] = 0.f;
    #pragma unroll
    for (int c4 = 0; c4 < 16; c4++) {
        float w0 = Wp[(c4*4 + 0) * 256 + t];
        float w1 = Wp[(c4*4 + 1) * 256 + t];
        float w2 = Wp[(c4*4 + 2) * 256 + t];
        float w3 = Wp[(c4*4 + 3) * 256 + t];
        #pragma unroll
        for (int r = 0; r < 32; r++) {
            float4 xv = Xs[r][c4];
            acc[r] += xv.x*w0 + xv.y*w1 + xv.z*w2 + xv.w*w3;
        }
    }
    #pragma unroll
    for (int r = 0; r < 32; r++)
        P[(size_t)(n0 + r) * 256 + t] = acc[r];
}

// ---------------- conv4 gather + fused dense shortcut ----------------
__global__ __launch_bounds__(64) void conv4_kernel(
    const float* __restrict__ P, const int* __restrict__ nbr,
    const float4* __restrict__ gF, const int* __restrict__ gI,
    const float* __restrict__ bc4, const float* __restrict__ out3,
    const float* __restrict__ Wd4, const float* __restrict__ bd4,
    float* __restrict__ out)
{
    __shared__ float red[2][3];
    int n = blockIdx.x, t = threadIdx.x;
    float a0 = 0.f, a1 = 0.f, a2 = 0.f;
    {
        float x = out3[(size_t)n * 64 + t];
        a0 += x * Wd4[t*3 + 0];
        a1 += x * Wd4[t*3 + 1];
        a2 += x * Wd4[t*3 + 2];
    }
    float4 g = gF[n*KNBR + t];
    if (g.w != 0.f) {
        int j = nbr[n*KNBR + t];
        const float4* Pj = (const float4*)(P + (size_t)j * 256);
        int base = gI[n*KNBR + t];
        float wx0 = (1.f - g.x) * g.w, wx1 = g.x * g.w;
        float wy0 = 1.f - g.y, wy1 = g.y;
        float wz0 = 1.f - g.z, wz1 = g.z;
        float wq[8] = {wx0*wy0*wz0, wx0*wy0*wz1, wx0*wy1*wz0, wx0*wy1*wz1,
                       wx1*wy0*wz0, wx1*wy0*wz1, wx1*wy1*wz0, wx1*wy1*wz1};
        const int off[8] = {0, 1, 4, 5, 16, 17, 20, 21};
        #pragma unroll
        for (int q = 0; q < 8; q++) {
            float4 p = Pj[base + off[q]];
            a0 += wq[q] * p.x; a1 += wq[q] * p.y; a2 += wq[q] * p.z;
        }
    }
    #pragma unroll
    for (int s = 16; s > 0; s >>= 1) {
        a0 += __shfl_down_sync(0xffffffff, a0, s);
        a1 += __shfl_down_sync(0xffffffff, a1, s);
        a2 += __shfl_down_sync(0xffffffff, a2, s);
    }
    if ((t & 31) == 0) { red[t>>5][0] = a0; red[t>>5][1] = a1; red[t>>5][2] = a2; }
    __syncthreads();
    if (t < 3) out[n*3 + t] = red[0][t] + red[1][t] + bc4[t] + bd4[t];
}

// ---------------- bf16 tensor GEMM: M-tile 128 (measured best) ----------------
#define STAGES 4
#define A_WLDS 20
#define B_WLDS 72
#define A_WSTAGE (128*A_WLDS)
#define B_WSTAGE (16*B_WLDS)
#define GEMM_SMEM (STAGES*(A_WSTAGE + B_WSTAGE)*4)

template<int HAS_ADD, int HAS_RES, int RELU>
__global__ __launch_bounds__(128) void gemm_mma(
    const __nv_bfloat16* __restrict__ Ag, const uint32_t* __restrict__ Wb,
    const float* __restrict__ bias, const float* __restrict__ addv,
    const float* __restrict__ resv, float* __restrict__ out,
    __nv_bfloat16* __restrict__ outb, int K)
{
    extern __shared__ uint32_t sm[];
    uint32_t* sA = sm;
    uint32_t* sB = sm + STAGES * A_WSTAGE;
    int tid = threadIdx.x, w = tid >> 5, lane = tid & 31;
    int g = lane >> 2, tg = lane & 3;
    int m0 = blockIdx.x * 128;
    int NIT = K >> 5;
    uint32_t sAu = smem_u32(sA), sBu = smem_u32(sB);

    auto load_stage = [&](int s, int c) {
        uint32_t ab = sAu + (uint32_t)s * A_WSTAGE * 4;
        const __nv_bfloat16* as = Ag + (size_t)m0 * K + c * 32;
        #pragma unroll
        for (int r = 0; r < 4; r++) {
            int idx = r * 128 + tid;
            int row = idx >> 2, seg = idx & 3;
            cp16(ab + (row * A_WLDS + seg * 4) * 4, as + (size_t)row * K + seg * 8);
        }
        uint32_t bb = sBu + (uint32_t)s * B_WSTAGE * 4;
        const uint32_t* bs = Wb + (size_t)c * 16 * 64;
        #pragma unroll
        for (int r = 0; r < 2; r++) {
            int idx = r * 128 + tid;
            int kp = idx >> 4, seg = idx & 15;
            cp16(bb + (kp * B_WLDS + seg * 4) * 4, bs + kp * 64 + seg * 4);
        }
    };

    float acc[2][8][4];
    #pragma unroll
    for (int mt = 0; mt < 2; mt++)
        #pragma unroll
        for (int nt = 0; nt < 8; nt++)
            #pragma unroll
            for (int q = 0; q < 4; q++) acc[mt][nt][q] = 0.f;

    #pragma unroll
    for (int s = 0; s < STAGES; s++) { load_stage(s, s); CP_COMMIT(); }

    for (int i = 0; i < NIT; i++) {
        asm volatile("cp.async.wait_group %0;" :: "n"(STAGES - 1));
        __syncthreads();
        const uint32_t* cA = sA + (i % STAGES) * A_WSTAGE;
        const uint32_t* cB = sB + (i % STAGES) * B_WSTAGE;
        #pragma unroll
        for (int q = 0; q < 2; q++) {
            uint32_t a[2][4], b[8][2];
            #pragma unroll
            for (int mt = 0; mt < 2; mt++) {
                int r = w * 32 + mt * 16 + g;
                a[mt][0] = cA[(r    ) * A_WLDS + 8*q + tg    ];
                a[mt][1] = cA[(r + 8) * A_WLDS + 8*q + tg    ];
                a[mt][2] = cA[(r    ) * A_WLDS + 8*q + tg + 4];
                a[mt][3] = cA[(r + 8) * A_WLDS + 8*q + tg + 4];
            }
            #pragma unroll
            for (int nt = 0; nt < 8; nt++) {
                b[nt][0] = cB[(8*q + tg    ) * B_WLDS + nt * 8 + g];
                b[nt][1] = cB[(8*q + tg + 4) * B_WLDS + nt * 8 + g];
            }
            #pragma unroll
            for (int mt = 0; mt < 2; mt++)
                #pragma unroll
                for (int nt = 0; nt < 8; nt++)
                    asm volatile(
                        "mma.sync.aligned.m16n8k16.row.col.f32.bf16.bf16.f32 "
                        "{%0,%1,%2,%3},{%4,%5,%6,%7},{%8,%9},{%0,%1,%2,%3};"
                        : "+f"(acc[mt][nt][0]), "+f"(acc[mt][nt][1]),
                          "+f"(acc[mt][nt][2]), "+f"(acc[mt][nt][3])
                        : "r"(a[mt][0]), "r"(a[mt][1]), "r"(a[mt][2]), "r"(a[mt][3]),
                          "r"(b[nt][0]), "r"(b[nt][1]));
        }
        __syncthreads();
        if (i + STAGES < NIT) load_stage(i % STAGES, i + STAGES);
        CP_COMMIT();
    }

    #pragma unroll
    for (int mt = 0; mt < 2; mt++) {
        #pragma unroll
        for (int nt = 0; nt < 8; nt++) {
            #pragma unroll
            for (int h = 0; h < 2; h++) {
                int m = m0 + w * 32 + mt * 16 + g + h * 8;
                int n0 = nt * 8 + 2 * tg;
                float lo = acc[mt][nt][h*2+0], hi = acc[mt][nt][h*2+1];
                float2 bb = *(const float2*)&bias[n0];
                lo += bb.x; hi += bb.y;
                if (HAS_ADD) {
                    float2 v = *(const float2*)&addv[(size_t)m*64 + n0];
                    lo += v.x; hi += v.y;
                }
                if (HAS_RES) {
                    float2 v = *(const float2*)&resv[(size_t)m*64 + n0];
                    lo += v.x; hi += v.y;
                }
                if (RELU) { lo = fmaxf(lo, 0.f); hi = fmaxf(hi, 0.f); }
                *(float2*)&out[(size_t)m*64 + n0] = make_float2(lo, hi);
                if (outb)
                    *(uint32_t*)&outb[(size_t)m*64 + n0] = bf16x2(hi, lo);
            }
        }
    }
}

// ---------------- dense GEMM ----------------
template<int CIN, int COUT, int RPT>
__global__ __launch_bounds__(COUT * (32 / RPT)) void dense_gemm(
    const float* __restrict__ X, const float* __restrict__ W,
    const float* __restrict__ b, float* __restrict__ Y,
    __nv_bfloat16* __restrict__ Yb, int ldY, int col0)
{
    constexpr int BD = COUT * (32 / RPT);
    __shared__ float Xs[32 * CIN];
    int t = threadIdx.x;
    int n0 = blockIdx.x * 32;
    for (int i = t; i < 32 * CIN; i += BD)
        Xs[i] = X[(size_t)n0 * CIN + i];
    __syncthreads();

    int o = t % COUT, rg = t / COUT;
    float acc[RPT];
    float bo = b[o];
    #pragma unroll
    for (int r = 0; r < RPT; r++) acc[r] = bo;
    #pragma unroll 4
    for (int c = 0; c < CIN; c++) {
        float wv = W[c * COUT + o];
        #pragma unroll
        for (int r = 0; r < RPT; r++)
            acc[r] += Xs[(rg * RPT + r) * CIN + c] * wv;
    }
    #pragma unroll
    for (int r = 0; r < RPT; r++) {
        size_t off = (size_t)(n0 + rg * RPT + r) * ldY + col0 + o;
        Y[off] = acc[r];
        if (Yb) Yb[off] = __float2bfloat16(acc[r]);
    }
}

// ---------------- launch (with multi-stream fork/join) ----------------
extern "C" void kernel_launch(void* const* d_in, const int* in_sizes, int n_in,
                              void* d_out, int out_size)
{
    const float* fluid_pos = (const float*)d_in[0];
    const float* wall_pos  = (const float*)d_in[1];
    const float* fluid_vel = (const float*)d_in[2];
    const float* wall_nv   = (const float*)d_in[3];
    const int*   nbr_wf    = (const int*)d_in[4];
    const void*  mask_wf   = d_in[5];
    const int*   nbr_ff    = (const int*)d_in[6];
    const void*  mask_ff   = d_in[7];
    const float* W_wall1 = (const float*)d_in[8];
    const float* b_wall1 = (const float*)d_in[9];
    const float* W_fluid1 = (const float*)d_in[10];
    const float* b_fluid1 = (const float*)d_in[11];
    const float* W_d1 = (const float*)d_in[12];
    const float* b_d1 = (const float*)d_in[13];
    const float* W_c2 = (const float*)d_in[14];
    const float* b_c2 = (const float*)d_in[15];
    const float* W_d2 = (const float*)d_in[16];
    const float* b_d2 = (const float*)d_in[17];
    const float* W_c3 = (const float*)d_in[18];
    const float* b_c3 = (const float*)d_in[19];
    const float* W_d3 = (const float*)d_in[20];
    const float* b_d3 = (const float*)d_in[21];
    const float* W_c4 = (const float*)d_in[22];
    const float* b_c4 = (const float*)d_in[23];
    const float* W_d4 = (const float*)d_in[24];
    const float* b_d4 = (const float*)d_in[25];

    void *pA, *pgFff, *pgIff, *pgFwf, *pgIwf, *pout1, *pout1b, *pout2, *pout2b,
         *pout3, *pdense, *pWb2, *pWb3, *pWp4;
    cudaGetSymbolAddress(&pA, g_A);
    cudaGetSymbolAddress(&pgFff, g_gF_ff);
    cudaGetSymbolAddress(&pgIff, g_gI_ff);
    cudaGetSymbolAddress(&pgFwf, g_gF_wf);
    cudaGetSymbolAddress(&pgIwf, g_gI_wf);
    cudaGetSymbolAddress(&pout1, g_out1);
    cudaGetSymbolAddress(&pout1b, g_out1b);
    cudaGetSymbolAddress(&pout2, g_out2);
    cudaGetSymbolAddress(&pout2b, g_out2b);
    cudaGetSymbolAddress(&pout3, g_out3);
    cudaGetSymbolAddress(&pdense, g_dense);
    cudaGetSymbolAddress(&pWb2, g_Wb2);
    cudaGetSymbolAddress(&pWb3, g_Wb3);
    cudaGetSymbolAddress(&pWp4, g_Wp4);
    void*   A     = pA;
    float4* gFff  = (float4*)pgFff;
    int*    gIff  = (int*)pgIff;
    float4* gFwf  = (float4*)pgFwf;
    int*    gIwf  = (int*)pgIwf;
    float*  out1  = (float*)pout1;
    __nv_bfloat16* out1b = (__nv_bfloat16*)pout1b;
    float*  out2  = (float*)pout2;
    __nv_bfloat16* out2b = (__nv_bfloat16*)pout2b;
    float*  out3  = (float*)pout3;
    float*  dense = (float*)pdense;
    uint32_t* Wb2 = (uint32_t*)pWb2;
    uint32_t* Wb3 = (uint32_t*)pWb3;
    float*  Wp4   = (float*)pWp4;

    cudaFuncSetAttribute(gemm_mma<1,0,1>, cudaFuncAttributeMaxDynamicSharedMemorySize, GEMM_SMEM);
    cudaFuncSetAttribute(gemm_mma<1,1,1>, cudaFuncAttributeMaxDynamicSharedMemorySize, GEMM_SMEM);

    // One-time side stream + events (created on the uncaptured correctness call).
    static cudaStream_t s1 = nullptr;
    static cudaEvent_t evRoot, evA, evB, evC, evD, evE;
    if (!s1) {
        cudaStreamCreateWithFlags(&s1, cudaStreamNonBlocking);
        cudaEventCreateWithFlags(&evRoot, cudaEventDisableTiming);
        cudaEventCreateWithFlags(&evA, cudaEventDisableTiming);
        cudaEventCreateWithFlags(&evB, cudaEventDisableTiming);
        cudaEventCreateWithFlags(&evC, cudaEventDisableTiming);
        cudaEventCreateWithFlags(&evD, cudaEventDisableTiming);
        cudaEventCreateWithFlags(&evE, cudaEventDisableTiming);
    }

    const int tot = NF * KNBR;

    // fork: side stream does pack + d1 while main does detect/geom/conv1
    cudaEventRecord(evRoot, 0);
    cudaStreamWaitEvent(s1, evRoot, 0);

    detect_mask_kernel<<<1, 1024>>>((const unsigned int*)mask_wf);
    geom2_kernel<<<(2*tot + 255)/256, 256>>>(fluid_pos, wall_pos,
                                             nbr_ff, mask_ff, gFff, gIff,
                                             nbr_wf, mask_wf, gFwf, gIwf);

    pack_all_kernel<<<(N_WB2 + N_WB3 + N_WP4 + 255)/256, 256, 0, s1>>>(
        W_c2, W_c3, W_c4, Wb2, Wb3, Wp4);
    dense_gemm<3, 32, 4><<<NF/32, 256, 0, s1>>>(fluid_vel, W_d1, b_d1, out1, out1b, 96, 64);
    cudaEventRecord(evA, s1);

    conv1_kernel<<<NF/4, 256>>>(wall_nv,   nbr_wf, gFwf, gIwf, W_wall1,  b_wall1,  out1, out1b, 0);
    conv1_kernel<<<NF/4, 256>>>(fluid_vel, nbr_ff, gFff, gIff, W_fluid1, b_fluid1, out1, out1b, 32);
    cudaStreamWaitEvent(0, evA, 0);         // layer-1 fully done on main

    // layer 2: d2 on s1 concurrent with cellgemm96 on main
    cudaEventRecord(evB, 0);
    cudaStreamWaitEvent(s1, evB, 0);
    dense_gemm<96, 64, 8><<<NF/32, 256, 0, s1>>>(out1, W_d2, b_d2, dense, nullptr, 64, 0);
    cudaEventRecord(evC, s1);
    cellgemm_kernel<96><<<NF, 128>>>(out1b, nbr_ff, gFff, gIff, (uint32_t*)A);
    cudaStreamWaitEvent(0, evC, 0);
    gemm_mma<1, 0, 1><<<NF/128, 128, GEMM_SMEM>>>((const __nv_bfloat16*)A, Wb2, b_c2, dense,
                                                  nullptr, out2, out2b, 6144);

    // layer 3: d3 on s1 concurrent with cellgemm64 on main
    cudaEventRecord(evD, 0);
    cudaStreamWaitEvent(s1, evD, 0);
    dense_gemm<64, 64, 8><<<NF/32, 256, 0, s1>>>(out2, W_d3, b_d3, dense, nullptr, 64, 0);
    cudaEventRecord(evE, s1);
    cellgemm_kernel<64><<<NF, 128>>>(out2b, nbr_ff, gFff, gIff, (uint32_t*)A);
    cudaStreamWaitEvent(0, evE, 0);
    gemm_mma<1, 1, 1><<<NF/128, 128, GEMM_SMEM>>>((const __nv_bfloat16*)A, Wb3, b_c3, dense,
                                                  out2, out3, nullptr, 4096);

    // layer 4
    pconv4_kernel<<<NF/32, 256>>>(out3, Wp4, (float*)A);
    conv4_kernel<<<NF, 64>>>((const float*)A, nbr_ff, gFff, gIff, b_c4,
                             out3, W_d4, b_d4, (float*)d_out);
}